// round 4
// baseline (speedup 1.0000x reference)
#include <cuda_runtime.h>

#define B_ 16
#define T_ 1024
#define D_ 1024
#define H_ 256
#define R_ 64
#define N_ 8

#define TT 64      // T rows per block tile
#define KC 32      // k-chunk

// Scratch (no allocations allowed -> device globals)
__device__ float g_losses[N_ * B_];
__device__ int   g_adp[B_];
__device__ float g_mid[(size_t)B_ * T_ * R_];

// ---------------------------------------------------------------------------
__global__ void zero_losses_kernel() {
    int i = threadIdx.x;
    if (i < N_ * B_) g_losses[i] = 0.f;
}

// ---------------------------------------------------------------------------
// Per (n, b, t-tile): h = relu(x@W_enc[n]+b_enc[n]) in SMEM, then
// recon = h@W_dec[n]+b_dec[n] in 256-col chunks, accumulate sum((recon-x)^2).
// Dynamic smem: hs[TT][H_] + ws[KC][256] + xs[TT][KC]
__global__ void disc_loss_kernel(const float* __restrict__ x,
                                 const float* __restrict__ W_enc,
                                 const float* __restrict__ b_enc,
                                 const float* __restrict__ W_dec,
                                 const float* __restrict__ b_dec) {
    extern __shared__ float smem[];
    float* hs = smem;                  // TT*H_  = 16384
    float* ws = hs + TT * H_;          // KC*256 =  8192
    float* xs = ws + KC * 256;         // TT*KC  =  2048

    const int n  = blockIdx.z;
    const int b  = blockIdx.y;
    const int t0 = blockIdx.x * TT;
    const int tid = threadIdx.x;
    const int tr = tid >> 5;           // 0..7  -> rows tr*8 .. tr*8+7
    const int tc = tid & 31;           // 0..31 -> cols tc + 32*j

    const float* xb = x + ((size_t)b * T_ + t0) * D_;

    float acc[8][8];
#pragma unroll
    for (int i = 0; i < 8; i++)
#pragma unroll
        for (int j = 0; j < 8; j++) acc[i][j] = 0.f;

    // ---- Phase 1: h tile ----
    for (int k0 = 0; k0 < D_; k0 += KC) {
        __syncthreads();
#pragma unroll
        for (int l = 0; l < (TT * KC) / 256; l++) {
            int idx = tid + l * 256;
            xs[idx] = xb[(size_t)(idx >> 5) * D_ + k0 + (idx & 31)];
        }
        const float* we = W_enc + ((size_t)n * D_ + k0) * H_;  // contiguous KC*H_ chunk
#pragma unroll
        for (int l = 0; l < (KC * H_) / 256; l++) {
            int idx = tid + l * 256;
            ws[idx] = we[idx];
        }
        __syncthreads();
#pragma unroll
        for (int kk = 0; kk < KC; kk++) {
            float a[8], w[8];
#pragma unroll
            for (int i = 0; i < 8; i++) a[i] = xs[(tr * 8 + i) * KC + kk];
#pragma unroll
            for (int j = 0; j < 8; j++) w[j] = ws[kk * 256 + tc + 32 * j];
#pragma unroll
            for (int i = 0; i < 8; i++)
#pragma unroll
                for (int j = 0; j < 8; j++)
                    acc[i][j] = fmaf(a[i], w[j], acc[i][j]);
        }
    }
    // relu + bias -> hs
#pragma unroll
    for (int i = 0; i < 8; i++) {
        int row = tr * 8 + i;
#pragma unroll
        for (int j = 0; j < 8; j++) {
            int col = tc + 32 * j;
            float v = acc[i][j] + b_enc[n * H_ + col];
            hs[row * H_ + col] = v > 0.f ? v : 0.f;
        }
    }
    __syncthreads();

    // ---- Phase 2: recon chunks + squared error ----
    float sumsq = 0.f;
    for (int dc = 0; dc < D_ / 256; dc++) {
        int d0 = dc * 256;
        float racc[8][8];
#pragma unroll
        for (int i = 0; i < 8; i++)
#pragma unroll
            for (int j = 0; j < 8; j++) racc[i][j] = 0.f;

        for (int h0 = 0; h0 < H_; h0 += KC) {
            __syncthreads();
            const float* wd = W_dec + ((size_t)n * H_ + h0) * D_ + d0;
#pragma unroll
            for (int l = 0; l < (KC * 256) / 256; l++) {
                int idx = tid + l * 256;
                ws[idx] = wd[(size_t)(idx >> 8) * D_ + (idx & 255)];
            }
            __syncthreads();
#pragma unroll
            for (int kk = 0; kk < KC; kk++) {
                float a[8], w[8];
#pragma unroll
                for (int i = 0; i < 8; i++) a[i] = hs[(tr * 8 + i) * H_ + h0 + kk];
#pragma unroll
                for (int j = 0; j < 8; j++) w[j] = ws[kk * 256 + tc + 32 * j];
#pragma unroll
                for (int i = 0; i < 8; i++)
#pragma unroll
                    for (int j = 0; j < 8; j++)
                        racc[i][j] = fmaf(a[i], w[j], racc[i][j]);
            }
        }
#pragma unroll
        for (int i = 0; i < 8; i++) {
            int row = tr * 8 + i;
#pragma unroll
            for (int j = 0; j < 8; j++) {
                int col = tc + 32 * j;
                float recon = racc[i][j] + b_dec[n * D_ + d0 + col];
                float diff = recon - xb[(size_t)row * D_ + d0 + col];
                sumsq = fmaf(diff, diff, sumsq);
            }
        }
    }

    // block reduction -> one atomicAdd per block
#pragma unroll
    for (int o = 16; o > 0; o >>= 1)
        sumsq += __shfl_down_sync(0xffffffffu, sumsq, o);
    __shared__ float red[8];
    if (tc == 0) red[tr] = sumsq;
    __syncthreads();
    if (tid == 0) {
        float s = 0.f;
#pragma unroll
        for (int i = 0; i < 8; i++) s += red[i];
        atomicAdd(&g_losses[n * B_ + b], s);
    }
}

// ---------------------------------------------------------------------------
__global__ void argmin_kernel(const int* __restrict__ connected_idx) {
    int b = threadIdx.x;
    if (b < B_) {
        float best = g_losses[b];
        int bi = 0;
        for (int n = 1; n < N_; n++) {
            float v = g_losses[n * B_ + b];
            if (v < best) { best = v; bi = n; }
        }
        g_adp[b] = connected_idx[bi];
    }
}

// ---------------------------------------------------------------------------
// mid = relu(x @ W_down[adp[b]] + b_down[adp[b]])  -> g_mid[B,T,R]
__global__ void mid_kernel(const float* __restrict__ x,
                           const float* __restrict__ W_down,
                           const float* __restrict__ b_down) {
    __shared__ float xs[TT * KC];
    __shared__ float wd[KC * R_];
    const int b  = blockIdx.y;
    const int t0 = blockIdx.x * TT;
    const int tid = threadIdx.x;
    const int tr = tid >> 4;   // 0..15 -> rows tr*4 .. tr*4+3
    const int tc = tid & 15;   // cols tc + 16*j
    const int a = g_adp[b];

    const float* xb = x + ((size_t)b * T_ + t0) * D_;
    const float* Wd = W_down + (size_t)a * D_ * R_;

    float acc[4][4];
#pragma unroll
    for (int i = 0; i < 4; i++)
#pragma unroll
        for (int j = 0; j < 4; j++) acc[i][j] = 0.f;

    for (int k0 = 0; k0 < D_; k0 += KC) {
        __syncthreads();
#pragma unroll
        for (int l = 0; l < (TT * KC) / 256; l++) {
            int idx = tid + l * 256;
            xs[idx] = xb[(size_t)(idx >> 5) * D_ + k0 + (idx & 31)];
        }
#pragma unroll
        for (int l = 0; l < (KC * R_) / 256; l++) {
            int idx = tid + l * 256;
            wd[idx] = Wd[(size_t)(k0 + (idx >> 6)) * R_ + (idx & 63)];
        }
        __syncthreads();
#pragma unroll
        for (int kk = 0; kk < KC; kk++) {
            float av[4], wv[4];
#pragma unroll
            for (int i = 0; i < 4; i++) av[i] = xs[(tr * 4 + i) * KC + kk];
#pragma unroll
            for (int j = 0; j < 4; j++) wv[j] = wd[kk * R_ + tc + 16 * j];
#pragma unroll
            for (int i = 0; i < 4; i++)
#pragma unroll
                for (int j = 0; j < 4; j++)
                    acc[i][j] = fmaf(av[i], wv[j], acc[i][j]);
        }
    }
#pragma unroll
    for (int i = 0; i < 4; i++) {
        int row = tr * 4 + i;
#pragma unroll
        for (int j = 0; j < 4; j++) {
            int col = tc + 16 * j;
            float v = acc[i][j] + b_down[a * R_ + col];
            g_mid[((size_t)b * T_ + t0 + row) * R_ + col] = v > 0.f ? v : 0.f;
        }
    }
}

// ---------------------------------------------------------------------------
// out = x@W_base + b_base + mid@W_up[adp] + b_up[adp]
__global__ void out_kernel(const float* __restrict__ x,
                           const float* __restrict__ W_base,
                           const float* __restrict__ b_base,
                           const float* __restrict__ W_up,
                           const float* __restrict__ b_up,
                           float* __restrict__ out) {
    __shared__ float ws[KC * 256];
    __shared__ float xs[TT * KC];
    const int b  = blockIdx.z;
    const int d0 = blockIdx.y * 256;
    const int t0 = blockIdx.x * TT;
    const int tid = threadIdx.x;
    const int tr = tid >> 5;
    const int tc = tid & 31;
    const int a = g_adp[b];

    const float* xb = x + ((size_t)b * T_ + t0) * D_;

    float acc[8][8];
#pragma unroll
    for (int i = 0; i < 8; i++)
#pragma unroll
        for (int j = 0; j < 8; j++) acc[i][j] = 0.f;

    // base GEMM, k = D_
    for (int k0 = 0; k0 < D_; k0 += KC) {
        __syncthreads();
#pragma unroll
        for (int l = 0; l < (TT * KC) / 256; l++) {
            int idx = tid + l * 256;
            xs[idx] = xb[(size_t)(idx >> 5) * D_ + k0 + (idx & 31)];
        }
        const float* wb = W_base + (size_t)k0 * D_ + d0;
#pragma unroll
        for (int l = 0; l < (KC * 256) / 256; l++) {
            int idx = tid + l * 256;
            ws[idx] = wb[(size_t)(idx >> 8) * D_ + (idx & 255)];
        }
        __syncthreads();
#pragma unroll
        for (int kk = 0; kk < KC; kk++) {
            float av[8], wv[8];
#pragma unroll
            for (int i = 0; i < 8; i++) av[i] = xs[(tr * 8 + i) * KC + kk];
#pragma unroll
            for (int j = 0; j < 8; j++) wv[j] = ws[kk * 256 + tc + 32 * j];
#pragma unroll
            for (int i = 0; i < 8; i++)
#pragma unroll
                for (int j = 0; j < 8; j++)
                    acc[i][j] = fmaf(av[i], wv[j], acc[i][j]);
        }
    }

    // adapter part, k = R_
    const float* mb = g_mid + ((size_t)b * T_ + t0) * R_;
    const float* Wu = W_up + (size_t)a * R_ * D_;
    for (int k0 = 0; k0 < R_; k0 += KC) {
        __syncthreads();
#pragma unroll
        for (int l = 0; l < (TT * KC) / 256; l++) {
            int idx = tid + l * 256;
            xs[idx] = mb[(size_t)(idx >> 5) * R_ + k0 + (idx & 31)];
        }
        const float* wu = Wu + (size_t)k0 * D_ + d0;
#pragma unroll
        for (int l = 0; l < (KC * 256) / 256; l++) {
            int idx = tid + l * 256;
            ws[idx] = wu[(size_t)(idx >> 8) * D_ + (idx & 255)];
        }
        __syncthreads();
#pragma unroll
        for (int kk = 0; kk < KC; kk++) {
            float av[8], wv[8];
#pragma unroll
            for (int i = 0; i < 8; i++) av[i] = xs[(tr * 8 + i) * KC + kk];
#pragma unroll
            for (int j = 0; j < 8; j++) wv[j] = ws[kk * 256 + tc + 32 * j];
#pragma unroll
            for (int i = 0; i < 8; i++)
#pragma unroll
                for (int j = 0; j < 8; j++)
                    acc[i][j] = fmaf(av[i], wv[j], acc[i][j]);
        }
    }

    // epilogue
#pragma unroll
    for (int i = 0; i < 8; i++) {
        int row = tr * 8 + i;
#pragma unroll
        for (int j = 0; j < 8; j++) {
            int col = tc + 32 * j;
            float v = acc[i][j] + b_base[d0 + col] + b_up[a * D_ + d0 + col];
            out[((size_t)b * T_ + t0 + row) * D_ + d0 + col] = v;
        }
    }
}

// ---------------------------------------------------------------------------
extern "C" void kernel_launch(void* const* d_in, const int* in_sizes, int n_in,
                              void* d_out, int out_size) {
    const float* x       = (const float*)d_in[0];
    const float* W_base  = (const float*)d_in[1];
    const float* b_base  = (const float*)d_in[2];
    const float* W_enc   = (const float*)d_in[3];
    const float* b_enc   = (const float*)d_in[4];
    const float* W_dec   = (const float*)d_in[5];
    const float* b_dec   = (const float*)d_in[6];
    const float* W_down  = (const float*)d_in[7];
    const float* b_down  = (const float*)d_in[8];
    const float* W_up    = (const float*)d_in[9];
    const float* b_up    = (const float*)d_in[10];
    const int*   cidx    = (const int*)d_in[11];
    float* out = (float*)d_out;

    const int disc_smem = (TT * H_ + KC * 256 + TT * KC) * (int)sizeof(float); // 104 KB
    cudaFuncSetAttribute(disc_loss_kernel,
                         cudaFuncAttributeMaxDynamicSharedMemorySize, disc_smem);

    zero_losses_kernel<<<1, 128>>>();

    dim3 g1(T_ / TT, B_, N_);
    disc_loss_kernel<<<g1, 256, disc_smem>>>(x, W_enc, b_enc, W_dec, b_dec);

    argmin_kernel<<<1, 32>>>(cidx);

    dim3 g2(T_ / TT, B_);
    mid_kernel<<<g2, 256>>>(x, W_down, b_down);

    dim3 g3(T_ / TT, D_ / 256, B_);
    out_kernel<<<g3, 256>>>(x, W_base, b_base, W_up, b_up, out);
}

// round 7
// speedup vs baseline: 3.0924x; 3.0924x over previous
#include <cuda_runtime.h>
#include <cstdint>

#define B_ 16
#define T_ 1024
#define D_ 1024
#define H_ 256
#define R_ 64
#define N_ 8

// SMEM strides (u32 units) chosen for conflict-free fragment reads
#define ASTR 36
#define BSTR 136
#define HSTR 260

// SMEM u32 offsets
#define AS0 0
#define AS1 4608                       // 128*36
#define BS0 9216
#define BS1 13568                      // + 32*136
#define HS  17920                      // out kernel ends here
#define SMEM_OUT_BYTES  (HS * 4)                    // 71680
#define SMEM_DISC_BYTES ((HS + 128 * HSTR) * 4)     // 204800

__device__ float g_losses[N_ * B_];
__device__ int   g_adp[B_];
__device__ float g_mid[(size_t)B_ * T_ * R_];

// ---------------- helpers ----------------
__device__ __forceinline__ uint32_t f2tf32(float f) {
    uint32_t u;
    asm("cvt.rna.tf32.f32 %0, %1;" : "=r"(u) : "f"(f));
    return u;
}
__device__ __forceinline__ void mma8(float c[4], const uint32_t a[4], const uint32_t b[2]) {
    asm volatile("mma.sync.aligned.m16n8k8.row.col.f32.tf32.tf32.f32 "
                 "{%0,%1,%2,%3}, {%4,%5,%6,%7}, {%8,%9}, {%0,%1,%2,%3};"
                 : "+f"(c[0]), "+f"(c[1]), "+f"(c[2]), "+f"(c[3])
                 : "r"(a[0]), "r"(a[1]), "r"(a[2]), "r"(a[3]),
                   "r"(b[0]), "r"(b[1]));
}

// Register staging payloads
struct St16 { float4 v[4]; };

// A slab: 128 rows x 32 cols from row-major src (leading dim ld)
__device__ __forceinline__ St16 ldA(const float* __restrict__ src, int ld, int tid) {
    St16 t;
#pragma unroll
    for (int l = 0; l < 4; l++) {
        int s = tid + l * 256, row = s >> 3, c4 = s & 7;
        t.v[l] = *reinterpret_cast<const float4*>(src + (size_t)row * ld + c4 * 4);
    }
    return t;
}
__device__ __forceinline__ void stA(uint32_t* As, const St16& t, int tid) {
#pragma unroll
    for (int l = 0; l < 4; l++) {
        int s = tid + l * 256, row = s >> 3, c4 = s & 7;
        uint4 u = make_uint4(f2tf32(t.v[l].x), f2tf32(t.v[l].y),
                             f2tf32(t.v[l].z), f2tf32(t.v[l].w));
        *reinterpret_cast<uint4*>(As + row * ASTR + c4 * 4) = u;
    }
}
// B slab: 32 rows (k) x 128 cols (n) from row-major src (leading dim ld)
__device__ __forceinline__ St16 ldB(const float* __restrict__ src, int ld, int tid) {
    St16 t;
#pragma unroll
    for (int l = 0; l < 4; l++) {
        int s = tid + l * 256, row = s >> 5, c4 = s & 31;
        t.v[l] = *reinterpret_cast<const float4*>(src + (size_t)row * ld + c4 * 4);
    }
    return t;
}
__device__ __forceinline__ void stB(uint32_t* Bs, const St16& t, int tid) {
#pragma unroll
    for (int l = 0; l < 4; l++) {
        int s = tid + l * 256, row = s >> 5, c4 = s & 31;
        uint4 u = make_uint4(f2tf32(t.v[l].x), f2tf32(t.v[l].y),
                             f2tf32(t.v[l].z), f2tf32(t.v[l].w));
        *reinterpret_cast<uint4*>(Bs + row * BSTR + c4 * 4) = u;
    }
}

// One K=32 chunk of warp-tile 64x32: A base pre-offset by warp M (and K), stride astr;
// Bsm = buffer base; lr = lane>>2, lk = lane&3, bn = CN + lr.
__device__ __forceinline__ void compute_chunk(const uint32_t* __restrict__ A, int astr,
                                              const uint32_t* __restrict__ Bsm,
                                              float (*c)[4][4], int lr, int lk, int bn) {
#pragma unroll
    for (int ks = 0; ks < 4; ks++) {
        uint32_t a[4][4], b[4][2];
#pragma unroll
        for (int mt = 0; mt < 4; mt++) {
            const uint32_t* ap = A + (mt * 16 + lr) * astr + ks * 8 + lk;
            a[mt][0] = ap[0];
            a[mt][1] = ap[8 * astr];
            a[mt][2] = ap[4];
            a[mt][3] = ap[8 * astr + 4];
        }
#pragma unroll
        for (int nt = 0; nt < 4; nt++) {
            const uint32_t* bp = Bsm + (ks * 8 + lk) * BSTR + bn + nt * 8;
            b[nt][0] = bp[0];
            b[nt][1] = bp[4 * BSTR];
        }
#pragma unroll
        for (int mt = 0; mt < 4; mt++)
#pragma unroll
            for (int nt = 0; nt < 4; nt++)
                mma8(c[mt][nt], a[mt], b[nt]);
    }
}

// ---------------- tiny kernels ----------------
__global__ void zero_losses_kernel() {
    int i = threadIdx.x;
    if (i < N_ * B_) g_losses[i] = 0.f;
}
__global__ void argmin_kernel(const int* __restrict__ connected_idx) {
    int b = threadIdx.x;
    if (b < B_) {
        float best = g_losses[b];
        int bi = 0;
        for (int n = 1; n < N_; n++) {
            float v = g_losses[n * B_ + b];
            if (v < best) { best = v; bi = n; }
        }
        g_adp[b] = connected_idx[bi];
    }
}

// ---------------- disc loss (mma.sync tf32) ----------------
// Per (n, b, 128-row tile): H = relu(x@W_enc+b_enc) kept in SMEM (tf32),
// then recon = H@W_dec per 128-col chunk; accumulate (recon+b_dec-x)^2.
__global__ __launch_bounds__(256, 1)
void disc_mma_kernel(const float* __restrict__ x,
                     const float* __restrict__ W_enc, const float* __restrict__ b_enc,
                     const float* __restrict__ W_dec, const float* __restrict__ b_dec) {
    extern __shared__ uint32_t sm[];
    const int tid = threadIdx.x, wid = tid >> 5, lane = tid & 31;
    const int wm = wid & 1, wn = wid >> 1;          // 2 x 4 warp grid
    const int RM = wm * 64, CN = wn * 32;
    const int lr = lane >> 2, lk = lane & 3;
    const int n = blockIdx.z, b = blockIdx.y, t0 = blockIdx.x * 128;

    const float* xb = x + ((size_t)b * T_ + t0) * D_;
    const float* We = W_enc + (size_t)n * D_ * H_;
    const float* Wd = W_dec + (size_t)n * H_ * D_;
    uint32_t* Hs = sm + HS;

    // ===== Phase 1: H = relu(x @ W_enc + b_enc), two 128-col passes =====
    for (int nc = 0; nc < 2; nc++) {
        float c[4][4][4];
#pragma unroll
        for (int mt = 0; mt < 4; mt++)
#pragma unroll
            for (int nt = 0; nt < 4; nt++)
#pragma unroll
                for (int i = 0; i < 4; i++) c[mt][nt][i] = 0.f;

        St16 ta = ldA(xb, D_, tid);
        St16 tb = ldB(We + nc * 128, H_, tid);
        stA(sm + AS0, ta, tid);
        stB(sm + BS0, tb, tid);
        __syncthreads();
        for (int kc = 0; kc < 32; kc++) {
            int s = kc & 1;
            if (kc + 1 < 32) {
                ta = ldA(xb + (kc + 1) * 32, D_, tid);
                tb = ldB(We + (size_t)(kc + 1) * 32 * H_ + nc * 128, H_, tid);
            }
            compute_chunk(sm + (s ? AS1 : AS0) + RM * ASTR, ASTR,
                          sm + (s ? BS1 : BS0), c, lr, lk, CN + lr);
            if (kc + 1 < 32) {
                int ns = (kc + 1) & 1;
                stA(sm + (ns ? AS1 : AS0), ta, tid);
                stB(sm + (ns ? BS1 : BS0), tb, tid);
            }
            __syncthreads();
        }
        // epilogue: bias + relu -> Hs (tf32)
#pragma unroll
        for (int mt = 0; mt < 4; mt++) {
            int r = RM + mt * 16 + lr;
#pragma unroll
            for (int nt = 0; nt < 4; nt++) {
                int col = nc * 128 + CN + nt * 8 + lk * 2;
                float be0 = __ldg(b_enc + n * H_ + col);
                float be1 = __ldg(b_enc + n * H_ + col + 1);
                float v0 = c[mt][nt][0] + be0, v1 = c[mt][nt][1] + be1;
                float v2 = c[mt][nt][2] + be0, v3 = c[mt][nt][3] + be1;
                Hs[r * HSTR + col]           = f2tf32(v0 > 0.f ? v0 : 0.f);
                Hs[r * HSTR + col + 1]       = f2tf32(v1 > 0.f ? v1 : 0.f);
                Hs[(r + 8) * HSTR + col]     = f2tf32(v2 > 0.f ? v2 : 0.f);
                Hs[(r + 8) * HSTR + col + 1] = f2tf32(v3 > 0.f ? v3 : 0.f);
            }
        }
        __syncthreads();
    }

    // ===== Phase 2: recon = H @ W_dec per 128-col d-chunk =====
    float sumsq = 0.f;
    for (int dc = 0; dc < 8; dc++) {
        float c[4][4][4];
#pragma unroll
        for (int mt = 0; mt < 4; mt++)
#pragma unroll
            for (int nt = 0; nt < 4; nt++)
#pragma unroll
                for (int i = 0; i < 4; i++) c[mt][nt][i] = 0.f;

        St16 tb = ldB(Wd + dc * 128, D_, tid);
        stB(sm + BS0, tb, tid);
        __syncthreads();
        for (int hc = 0; hc < 8; hc++) {
            int s = hc & 1;
            if (hc + 1 < 8)
                tb = ldB(Wd + (size_t)(hc + 1) * 32 * D_ + dc * 128, D_, tid);
            compute_chunk(Hs + RM * HSTR + hc * 32, HSTR,
                          sm + (s ? BS1 : BS0), c, lr, lk, CN + lr);
            if (hc + 1 < 8) {
                int ns = (hc + 1) & 1;
                stB(sm + (ns ? BS1 : BS0), tb, tid);
            }
            __syncthreads();
        }
        // epilogue: (recon + b_dec - x)^2
#pragma unroll
        for (int mt = 0; mt < 4; mt++) {
            int r = RM + mt * 16 + lr;
#pragma unroll
            for (int nt = 0; nt < 4; nt++) {
                int col = dc * 128 + CN + nt * 8 + lk * 2;
                float bd0 = __ldg(b_dec + n * D_ + col);
                float bd1 = __ldg(b_dec + n * D_ + col + 1);
                float2 x0 = *reinterpret_cast<const float2*>(xb + (size_t)r * D_ + col);
                float2 x1 = *reinterpret_cast<const float2*>(xb + (size_t)(r + 8) * D_ + col);
                float e0 = c[mt][nt][0] + bd0 - x0.x;
                float e1 = c[mt][nt][1] + bd1 - x0.y;
                float e2 = c[mt][nt][2] + bd0 - x1.x;
                float e3 = c[mt][nt][3] + bd1 - x1.y;
                sumsq = fmaf(e0, e0, sumsq);
                sumsq = fmaf(e1, e1, sumsq);
                sumsq = fmaf(e2, e2, sumsq);
                sumsq = fmaf(e3, e3, sumsq);
            }
        }
    }

#pragma unroll
    for (int o = 16; o > 0; o >>= 1)
        sumsq += __shfl_down_sync(0xffffffffu, sumsq, o);
    __shared__ float red[8];
    if (lane == 0) red[wid] = sumsq;
    __syncthreads();
    if (tid == 0) {
        float s = 0.f;
#pragma unroll
        for (int i = 0; i < 8; i++) s += red[i];
        atomicAdd(&g_losses[n * B_ + b], s);
    }
}

// ---------------- mid (SIMT fp32) ----------------
__global__ void mid_kernel(const float* __restrict__ x,
                           const float* __restrict__ W_down,
                           const float* __restrict__ b_down) {
    __shared__ float xs[64 * 32];
    __shared__ float wd[32 * R_];
    const int b = blockIdx.y, t0 = blockIdx.x * 64;
    const int tid = threadIdx.x;
    const int tr = tid >> 4, tc = tid & 15;
    const int a = g_adp[b];
    const float* xb = x + ((size_t)b * T_ + t0) * D_;
    const float* Wd = W_down + (size_t)a * D_ * R_;

    float acc[4][4];
#pragma unroll
    for (int i = 0; i < 4; i++)
#pragma unroll
        for (int j = 0; j < 4; j++) acc[i][j] = 0.f;

    for (int k0 = 0; k0 < D_; k0 += 32) {
        __syncthreads();
#pragma unroll
        for (int l = 0; l < 8; l++) {
            int idx = tid + l * 256;
            xs[idx] = xb[(size_t)(idx >> 5) * D_ + k0 + (idx & 31)];
        }
#pragma unroll
        for (int l = 0; l < 8; l++) {
            int idx = tid + l * 256;
            wd[idx] = Wd[(size_t)(k0 + (idx >> 6)) * R_ + (idx & 63)];
        }
        __syncthreads();
#pragma unroll
        for (int kk = 0; kk < 32; kk++) {
            float av[4], wv[4];
#pragma unroll
            for (int i = 0; i < 4; i++) av[i] = xs[(tr * 4 + i) * 32 + kk];
#pragma unroll
            for (int j = 0; j < 4; j++) wv[j] = wd[kk * R_ + tc + 16 * j];
#pragma unroll
            for (int i = 0; i < 4; i++)
#pragma unroll
                for (int j = 0; j < 4; j++)
                    acc[i][j] = fmaf(av[i], wv[j], acc[i][j]);
        }
    }
#pragma unroll
    for (int i = 0; i < 4; i++) {
        int rr = tr * 4 + i;
#pragma unroll
        for (int j = 0; j < 4; j++) {
            int col = tc + 16 * j;
            float v = acc[i][j] + b_down[a * R_ + col];
            g_mid[((size_t)b * T_ + t0 + rr) * R_ + col] = v > 0.f ? v : 0.f;
        }
    }
}

// ---------------- out = x@W_base + mid@W_up + biases (mma.sync tf32) ----------------
__global__ __launch_bounds__(256, 1)
void out_mma_kernel(const float* __restrict__ x,
                    const float* __restrict__ W_base, const float* __restrict__ b_base,
                    const float* __restrict__ W_up,  const float* __restrict__ b_up,
                    float* __restrict__ out) {
    extern __shared__ uint32_t sm[];
    const int tid = threadIdx.x, wid = tid >> 5, lane = tid & 31;
    const int wm = wid & 1, wn = wid >> 1;
    const int RM = wm * 64, CN = wn * 32;
    const int lr = lane >> 2, lk = lane & 3;
    const int b = blockIdx.z, e0 = blockIdx.y * 128, t0 = blockIdx.x * 128;
    const int a = g_adp[b];

    const float* xb = x + ((size_t)b * T_ + t0) * D_;
    const float* mb = g_mid + ((size_t)b * T_ + t0) * R_;
    const float* Wu = W_up + (size_t)a * R_ * D_;

    float c[4][4][4];
#pragma unroll
    for (int mt = 0; mt < 4; mt++)
#pragma unroll
        for (int nt = 0; nt < 4; nt++)
#pragma unroll
            for (int i = 0; i < 4; i++) c[mt][nt][i] = 0.f;

    const int NC = 34;   // 32 base + 2 adapter K-chunks, one accumulator
    St16 ta = ldA(xb, D_, tid);
    St16 tb = ldB(W_base + e0, D_, tid);
    stA(sm + AS0, ta, tid);
    stB(sm + BS0, tb, tid);
    __syncthreads();
    for (int kc = 0; kc < NC; kc++) {
        int s = kc & 1;
        if (kc + 1 < 32) {
            ta = ldA(xb + (kc + 1) * 32, D_, tid);
            tb = ldB(W_base + (size_t)(kc + 1) * 32 * D_ + e0, D_, tid);
        } else if (kc + 1 < NC) {
            int k0 = (kc + 1 - 32) * 32;
            ta = ldA(mb + k0, R_, tid);
            tb = ldB(Wu + (size_t)k0 * D_ + e0, D_, tid);
        }
        compute_chunk(sm + (s ? AS1 : AS0) + RM * ASTR, ASTR,
                      sm + (s ? BS1 : BS0), c, lr, lk, CN + lr);
        if (kc + 1 < NC) {
            int ns = (kc + 1) & 1;
            stA(sm + (ns ? AS1 : AS0), ta, tid);
            stB(sm + (ns ? BS1 : BS0), tb, tid);
        }
        __syncthreads();
    }

    // epilogue: + b_base + b_up -> out (float2 stores)
#pragma unroll
    for (int mt = 0; mt < 4; mt++) {
        int r = RM + mt * 16 + lr;
#pragma unroll
        for (int nt = 0; nt < 4; nt++) {
            int col = e0 + CN + nt * 8 + lk * 2;
            float bb0 = __ldg(b_base + col) + __ldg(b_up + a * D_ + col);
            float bb1 = __ldg(b_base + col + 1) + __ldg(b_up + a * D_ + col + 1);
            float2 v0 = make_float2(c[mt][nt][0] + bb0, c[mt][nt][1] + bb1);
            float2 v1 = make_float2(c[mt][nt][2] + bb0, c[mt][nt][3] + bb1);
            *reinterpret_cast<float2*>(out + ((size_t)b * T_ + t0 + r) * D_ + col) = v0;
            *reinterpret_cast<float2*>(out + ((size_t)b * T_ + t0 + r + 8) * D_ + col) = v1;
        }
    }
}

// ---------------------------------------------------------------------------
extern "C" void kernel_launch(void* const* d_in, const int* in_sizes, int n_in,
                              void* d_out, int out_size) {
    const float* x      = (const float*)d_in[0];
    const float* W_base = (const float*)d_in[1];
    const float* b_base = (const float*)d_in[2];
    const float* W_enc  = (const float*)d_in[3];
    const float* b_enc  = (const float*)d_in[4];
    const float* W_dec  = (const float*)d_in[5];
    const float* b_dec  = (const float*)d_in[6];
    const float* W_down = (const float*)d_in[7];
    const float* b_down = (const float*)d_in[8];
    const float* W_up   = (const float*)d_in[9];
    const float* b_up   = (const float*)d_in[10];
    const int*   cidx   = (const int*)d_in[11];
    float* out = (float*)d_out;

    cudaFuncSetAttribute(disc_mma_kernel, cudaFuncAttributeMaxDynamicSharedMemorySize, SMEM_DISC_BYTES);
    cudaFuncSetAttribute(out_mma_kernel,  cudaFuncAttributeMaxDynamicSharedMemorySize, SMEM_OUT_BYTES);

    zero_losses_kernel<<<1, 128>>>();

    dim3 g1(T_ / 128, B_, N_);
    disc_mma_kernel<<<g1, 256, SMEM_DISC_BYTES>>>(x, W_enc, b_enc, W_dec, b_dec);

    argmin_kernel<<<1, 32>>>(cidx);

    dim3 g2(T_ / 64, B_);
    mid_kernel<<<g2, 256>>>(x, W_down, b_down);

    dim3 g3(T_ / 128, D_ / 128, B_);
    out_mma_kernel<<<g3, 256, SMEM_OUT_BYTES>>>(x, W_base, b_base, W_up, b_up, out);
}

// round 9
// speedup vs baseline: 4.3101x; 1.3937x over previous
#include <cuda_runtime.h>
#include <cuda_fp16.h>
#include <cstdint>

#define B_ 16
#define T_ 1024
#define D_ 1024
#define H_ 256
#define R_ 64
#define N_ 8

// SMEM strides in u32 units (u32 = packed half2, k-pair)
#define ASTR 20     // A: 128 rows x 16 k2 (+pad)   (20*lr+lk)%32 bijective
#define BSTR 132    // B: 16 k2 x 128 n (+pad)      (132*lk+lr)%32 = (4lk+lr)%32 bijective
#define HSTR 132    // H: 128 rows x 128 k2 (+pad)  (132*lr+lk)%32 = (4lr+lk)%32 bijective

// SMEM u32 offsets
#define AS0 0
#define AS1 2560                 // 128*20
#define BS0 5120
#define BS1 7232                 // +16*132
#define HS  9344
#define SMEM_OUT_BYTES  (HS * 4)                    // 37376
#define SMEM_DISC_BYTES ((HS + 128 * HSTR) * 4)     // 104960

__device__ float g_losses[N_ * B_];
__device__ int   g_adp[B_];
__device__ float g_mid[(size_t)B_ * T_ * R_];

// ---------------- helpers ----------------
__device__ __forceinline__ uint32_t packh2(float lo, float hi) {
    __half2 h = __floats2half2_rn(lo, hi);   // .x -> low 16 bits
    return *reinterpret_cast<uint32_t*>(&h);
}
__device__ __forceinline__ void mma16(float c[4], const uint32_t a[4], const uint32_t b[2]) {
    asm volatile("mma.sync.aligned.m16n8k16.row.col.f32.f16.f16.f32 "
                 "{%0,%1,%2,%3}, {%4,%5,%6,%7}, {%8,%9}, {%0,%1,%2,%3};"
                 : "+f"(c[0]), "+f"(c[1]), "+f"(c[2]), "+f"(c[3])
                 : "r"(a[0]), "r"(a[1]), "r"(a[2]), "r"(a[3]),
                   "r"(b[0]), "r"(b[1]));
}

// Register staging payloads
struct StA { float4 v[4]; };            // A slab: 128 rows x 32 k (f32 source)
struct StB { float4 p[2], q[2]; };      // B slab: 32 k x 128 n   (f32 source)

__device__ __forceinline__ StA ldA(const float* __restrict__ src, int ld, int tid) {
    StA t;
#pragma unroll
    for (int l = 0; l < 4; l++) {
        int s = tid + l * 256, row = s >> 3, c4 = s & 7;
        t.v[l] = *reinterpret_cast<const float4*>(src + (size_t)row * ld + c4 * 4);
    }
    return t;
}
__device__ __forceinline__ void stA(uint32_t* As, const StA& t, int tid) {
#pragma unroll
    for (int l = 0; l < 4; l++) {
        int s = tid + l * 256, row = s >> 3, c4 = s & 7;
        uint2 u = make_uint2(packh2(t.v[l].x, t.v[l].y), packh2(t.v[l].z, t.v[l].w));
        *reinterpret_cast<uint2*>(As + row * ASTR + c4 * 2) = u;
    }
}
// B source rows k = 2*k2, 2*k2+1; dest Bs32[k2][n] = {B[2k2][n] lo, B[2k2+1][n] hi}
__device__ __forceinline__ StB ldB(const float* __restrict__ src, int ld, int tid) {
    StB t;
#pragma unroll
    for (int l = 0; l < 2; l++) {
        int o = tid + l * 256, k2 = o >> 5, n4 = o & 31;
        t.p[l] = *reinterpret_cast<const float4*>(src + (size_t)(2 * k2) * ld + n4 * 4);
        t.q[l] = *reinterpret_cast<const float4*>(src + (size_t)(2 * k2 + 1) * ld + n4 * 4);
    }
    return t;
}
__device__ __forceinline__ void stB(uint32_t* Bs, const StB& t, int tid) {
#pragma unroll
    for (int l = 0; l < 2; l++) {
        int o = tid + l * 256, k2 = o >> 5, n4 = o & 31;
        uint4 u = make_uint4(packh2(t.p[l].x, t.q[l].x), packh2(t.p[l].y, t.q[l].y),
                             packh2(t.p[l].z, t.q[l].z), packh2(t.p[l].w, t.q[l].w));
        *reinterpret_cast<uint4*>(Bs + k2 * BSTR + n4 * 4) = u;
    }
}

// One K=32 chunk of warp tile 64x32 (2 ks-steps of K=16).
// A pre-offset to warp M rows (u32/k2 units, stride astr); bn = CN + lr.
__device__ __forceinline__ void compute_chunk(const uint32_t* __restrict__ A, int astr,
                                              const uint32_t* __restrict__ Bsm, int bstr,
                                              float (*c)[4][4], int lr, int lk, int bn) {
#pragma unroll
    for (int ks = 0; ks < 2; ks++) {
        uint32_t a[4][4], b[4][2];
#pragma unroll
        for (int mt = 0; mt < 4; mt++) {
            const uint32_t* ap = A + (mt * 16 + lr) * astr + ks * 8 + lk;
            a[mt][0] = ap[0];
            a[mt][1] = ap[8 * astr];
            a[mt][2] = ap[4];
            a[mt][3] = ap[8 * astr + 4];
        }
#pragma unroll
        for (int nt = 0; nt < 4; nt++) {
            const uint32_t* bp = Bsm + (ks * 8 + lk) * bstr + bn + nt * 8;
            b[nt][0] = bp[0];
            b[nt][1] = bp[4 * bstr];
        }
#pragma unroll
        for (int mt = 0; mt < 4; mt++)
#pragma unroll
            for (int nt = 0; nt < 4; nt++)
                mma16(c[mt][nt], a[mt], b[nt]);
    }
}

// ---------------- tiny kernels ----------------
__global__ void zero_losses_kernel() {
    int i = threadIdx.x;
    if (i < N_ * B_) g_losses[i] = 0.f;
}
__global__ void argmin_kernel(const int* __restrict__ connected_idx) {
    int b = threadIdx.x;
    if (b < B_) {
        float best = g_losses[b];
        int bi = 0;
        for (int n = 1; n < N_; n++) {
            float v = g_losses[n * B_ + b];
            if (v < best) { best = v; bi = n; }
        }
        g_adp[b] = connected_idx[bi];
    }
}

// ---------------- disc loss (mma.sync fp16, f32 accum) ----------------
__global__ __launch_bounds__(256, 1)
void disc_mma_kernel(const float* __restrict__ x,
                     const float* __restrict__ W_enc, const float* __restrict__ b_enc,
                     const float* __restrict__ W_dec, const float* __restrict__ b_dec) {
    extern __shared__ uint32_t sm[];
    const int tid = threadIdx.x, wid = tid >> 5, lane = tid & 31;
    const int wm = wid & 1, wn = wid >> 1;          // 2 x 4 warp grid
    const int RM = wm * 64, CN = wn * 32;
    const int lr = lane >> 2, lk = lane & 3;
    const int n = blockIdx.z, b = blockIdx.y, t0 = blockIdx.x * 128;

    const float* xb = x + ((size_t)b * T_ + t0) * D_;
    const float* We = W_enc + (size_t)n * D_ * H_;
    const float* Wd = W_dec + (size_t)n * H_ * D_;
    uint32_t* Hs = sm + HS;

    // ===== Phase 1: H = relu(x @ W_enc + b_enc), two 128-col passes =====
    for (int nc = 0; nc < 2; nc++) {
        float c[4][4][4];
#pragma unroll
        for (int mt = 0; mt < 4; mt++)
#pragma unroll
            for (int nt = 0; nt < 4; nt++)
#pragma unroll
                for (int i = 0; i < 4; i++) c[mt][nt][i] = 0.f;

        StA ta = ldA(xb, D_, tid);
        StB tb = ldB(We + nc * 128, H_, tid);
        stA(sm + AS0, ta, tid);
        stB(sm + BS0, tb, tid);
        __syncthreads();
        for (int kc = 0; kc < 32; kc++) {
            int s = kc & 1;
            if (kc + 1 < 32) {
                ta = ldA(xb + (kc + 1) * 32, D_, tid);
                tb = ldB(We + (size_t)(kc + 1) * 32 * H_ + nc * 128, H_, tid);
            }
            compute_chunk(sm + (s ? AS1 : AS0) + RM * ASTR, ASTR,
                          sm + (s ? BS1 : BS0), BSTR, c, lr, lk, CN + lr);
            if (kc + 1 < 32) {
                int ns = (kc + 1) & 1;
                stA(sm + (ns ? AS1 : AS0), ta, tid);
                stB(sm + (ns ? BS1 : BS0), tb, tid);
            }
            __syncthreads();
        }
        // epilogue: bias + relu -> Hs (fp16 pairs)
#pragma unroll
        for (int mt = 0; mt < 4; mt++) {
            int r = RM + mt * 16 + lr;
#pragma unroll
            for (int nt = 0; nt < 4; nt++) {
                int col = nc * 128 + CN + nt * 8 + lk * 2;   // even
                float be0 = __ldg(b_enc + n * H_ + col);
                float be1 = __ldg(b_enc + n * H_ + col + 1);
                float v0 = c[mt][nt][0] + be0, v1 = c[mt][nt][1] + be1;
                float v2 = c[mt][nt][2] + be0, v3 = c[mt][nt][3] + be1;
                Hs[r * HSTR + (col >> 1)]       = packh2(v0 > 0.f ? v0 : 0.f, v1 > 0.f ? v1 : 0.f);
                Hs[(r + 8) * HSTR + (col >> 1)] = packh2(v2 > 0.f ? v2 : 0.f, v3 > 0.f ? v3 : 0.f);
            }
        }
        __syncthreads();
    }

    // ===== Phase 2: recon = H @ W_dec per 128-col d-chunk =====
    float sumsq = 0.f;
    for (int dc = 0; dc < 8; dc++) {
        float c[4][4][4];
#pragma unroll
        for (int mt = 0; mt < 4; mt++)
#pragma unroll
            for (int nt = 0; nt < 4; nt++)
#pragma unroll
                for (int i = 0; i < 4; i++) c[mt][nt][i] = 0.f;

        StB tb = ldB(Wd + dc * 128, D_, tid);
        stB(sm + BS0, tb, tid);
        __syncthreads();
        for (int hc = 0; hc < 8; hc++) {
            int s = hc & 1;
            if (hc + 1 < 8)
                tb = ldB(Wd + (size_t)(hc + 1) * 32 * D_ + dc * 128, D_, tid);
            compute_chunk(Hs + RM * HSTR + hc * 16, HSTR,
                          sm + (s ? BS1 : BS0), BSTR, c, lr, lk, CN + lr);
            if (hc + 1 < 8) {
                int ns = (hc + 1) & 1;
                stB(sm + (ns ? BS1 : BS0), tb, tid);
            }
            __syncthreads();
        }
        // epilogue: (recon + b_dec - x)^2
#pragma unroll
        for (int mt = 0; mt < 4; mt++) {
            int r = RM + mt * 16 + lr;
#pragma unroll
            for (int nt = 0; nt < 4; nt++) {
                int col = dc * 128 + CN + nt * 8 + lk * 2;
                float bd0 = __ldg(b_dec + n * D_ + col);
                float bd1 = __ldg(b_dec + n * D_ + col + 1);
                float2 x0 = *reinterpret_cast<const float2*>(xb + (size_t)r * D_ + col);
                float2 x1 = *reinterpret_cast<const float2*>(xb + (size_t)(r + 8) * D_ + col);
                float e0 = c[mt][nt][0] + bd0 - x0.x;
                float e1 = c[mt][nt][1] + bd1 - x0.y;
                float e2 = c[mt][nt][2] + bd0 - x1.x;
                float e3 = c[mt][nt][3] + bd1 - x1.y;
                sumsq = fmaf(e0, e0, sumsq);
                sumsq = fmaf(e1, e1, sumsq);
                sumsq = fmaf(e2, e2, sumsq);
                sumsq = fmaf(e3, e3, sumsq);
            }
        }
    }

#pragma unroll
    for (int o = 16; o > 0; o >>= 1)
        sumsq += __shfl_down_sync(0xffffffffu, sumsq, o);
    __shared__ float red[8];
    if (lane == 0) red[wid] = sumsq;
    __syncthreads();
    if (tid == 0) {
        float s = 0.f;
#pragma unroll
        for (int i = 0; i < 8; i++) s += red[i];
        atomicAdd(&g_losses[n * B_ + b], s);
    }
}

// ---------------- mid (SIMT fp32, known-good) ----------------
__global__ void mid_kernel(const float* __restrict__ x,
                           const float* __restrict__ W_down,
                           const float* __restrict__ b_down) {
    __shared__ float xs[64 * 32];
    __shared__ float wd[32 * R_];
    const int b = blockIdx.y, t0 = blockIdx.x * 64;
    const int tid = threadIdx.x;
    const int tr = tid >> 4, tc = tid & 15;
    const int a = g_adp[b];
    const float* xb = x + ((size_t)b * T_ + t0) * D_;
    const float* Wd = W_down + (size_t)a * D_ * R_;

    float acc[4][4];
#pragma unroll
    for (int i = 0; i < 4; i++)
#pragma unroll
        for (int j = 0; j < 4; j++) acc[i][j] = 0.f;

    for (int k0 = 0; k0 < D_; k0 += 32) {
        __syncthreads();
#pragma unroll
        for (int l = 0; l < 8; l++) {
            int idx = tid + l * 256;
            xs[idx] = xb[(size_t)(idx >> 5) * D_ + k0 + (idx & 31)];
        }
#pragma unroll
        for (int l = 0; l < 8; l++) {
            int idx = tid + l * 256;
            wd[idx] = Wd[(size_t)(k0 + (idx >> 6)) * R_ + (idx & 63)];
        }
        __syncthreads();
#pragma unroll
        for (int kk = 0; kk < 32; kk++) {
            float av[4], wv[4];
#pragma unroll
            for (int i = 0; i < 4; i++) av[i] = xs[(tr * 4 + i) * 32 + kk];
#pragma unroll
            for (int j = 0; j < 4; j++) wv[j] = wd[kk * R_ + tc + 16 * j];
#pragma unroll
            for (int i = 0; i < 4; i++)
#pragma unroll
                for (int j = 0; j < 4; j++)
                    acc[i][j] = fmaf(av[i], wv[j], acc[i][j]);
        }
    }
#pragma unroll
    for (int i = 0; i < 4; i++) {
        int rr = tr * 4 + i;
#pragma unroll
        for (int j = 0; j < 4; j++) {
            int col = tc + 16 * j;
            float v = acc[i][j] + b_down[a * R_ + col];
            g_mid[((size_t)b * T_ + t0 + rr) * R_ + col] = v > 0.f ? v : 0.f;
        }
    }
}

// ---------------- out = x@W_base + mid@W_up + biases (mma.sync fp16) ----------------
__global__ __launch_bounds__(256, 1)
void out_mma_kernel(const float* __restrict__ x,
                    const float* __restrict__ W_base, const float* __restrict__ b_base,
                    const float* __restrict__ W_up,  const float* __restrict__ b_up,
                    float* __restrict__ out) {
    extern __shared__ uint32_t sm[];
    const int tid = threadIdx.x, wid = tid >> 5, lane = tid & 31;
    const int wm = wid & 1, wn = wid >> 1;
    const int RM = wm * 64, CN = wn * 32;
    const int lr = lane >> 2, lk = lane & 3;
    const int b = blockIdx.z, e0 = blockIdx.y * 128, t0 = blockIdx.x * 128;
    const int a = g_adp[b];

    const float* xb = x + ((size_t)b * T_ + t0) * D_;
    const float* mb = g_mid + ((size_t)b * T_ + t0) * R_;
    const float* Wu = W_up + (size_t)a * R_ * D_;

    float c[4][4][4];
#pragma unroll
    for (int mt = 0; mt < 4; mt++)
#pragma unroll
        for (int nt = 0; nt < 4; nt++)
#pragma unroll
            for (int i = 0; i < 4; i++) c[mt][nt][i] = 0.f;

    const int NC = 34;   // 32 base + 2 adapter K-chunks, one accumulator
    StA ta = ldA(xb, D_, tid);
    StB tb = ldB(W_base + e0, D_, tid);
    stA(sm + AS0, ta, tid);
    stB(sm + BS0, tb, tid);
    __syncthreads();
    for (int kc = 0; kc < NC; kc++) {
        int s = kc & 1;
        if (kc + 1 < 32) {
            ta = ldA(xb + (kc + 1) * 32, D_, tid);
            tb = ldB(W_base + (size_t)(kc + 1) * 32 * D_ + e0, D_, tid);
        } else if (kc + 1 < NC) {
            int k0 = (kc + 1 - 32) * 32;
            ta = ldA(mb + k0, R_, tid);
            tb = ldB(Wu + (size_t)k0 * D_ + e0, D_, tid);
        }
        compute_chunk(sm + (s ? AS1 : AS0) + RM * ASTR, ASTR,
                      sm + (s ? BS1 : BS0), BSTR, c, lr, lk, CN + lr);
        if (kc + 1 < NC) {
            int ns = (kc + 1) & 1;
            stA(sm + (ns ? AS1 : AS0), ta, tid);
            stB(sm + (ns ? BS1 : BS0), tb, tid);
        }
        __syncthreads();
    }

    // epilogue: + b_base + b_up -> out (float2 stores)
#pragma unroll
    for (int mt = 0; mt < 4; mt++) {
        int r = RM + mt * 16 + lr;
#pragma unroll
        for (int nt = 0; nt < 4; nt++) {
            int col = e0 + CN + nt * 8 + lk * 2;
            float bb0 = __ldg(b_base + col) + __ldg(b_up + a * D_ + col);
            float bb1 = __ldg(b_base + col + 1) + __ldg(b_up + a * D_ + col + 1);
            float2 v0 = make_float2(c[mt][nt][0] + bb0, c[mt][nt][1] + bb1);
            float2 v1 = make_float2(c[mt][nt][2] + bb0, c[mt][nt][3] + bb1);
            *reinterpret_cast<float2*>(out + ((size_t)b * T_ + t0 + r) * D_ + col) = v0;
            *reinterpret_cast<float2*>(out + ((size_t)b * T_ + t0 + r + 8) * D_ + col) = v1;
        }
    }
}

// ---------------------------------------------------------------------------
extern "C" void kernel_launch(void* const* d_in, const int* in_sizes, int n_in,
                              void* d_out, int out_size) {
    const float* x      = (const float*)d_in[0];
    const float* W_base = (const float*)d_in[1];
    const float* b_base = (const float*)d_in[2];
    const float* W_enc  = (const float*)d_in[3];
    const float* b_enc  = (const float*)d_in[4];
    const float* W_dec  = (const float*)d_in[5];
    const float* b_dec  = (const float*)d_in[6];
    const float* W_down = (const float*)d_in[7];
    const float* b_down = (const float*)d_in[8];
    const float* W_up   = (const float*)d_in[9];
    const float* b_up   = (const float*)d_in[10];
    const int*   cidx   = (const int*)d_in[11];
    float* out = (float*)d_out;

    cudaFuncSetAttribute(disc_mma_kernel, cudaFuncAttributeMaxDynamicSharedMemorySize, SMEM_DISC_BYTES);
    cudaFuncSetAttribute(out_mma_kernel,  cudaFuncAttributeMaxDynamicSharedMemorySize, SMEM_OUT_BYTES);

    zero_losses_kernel<<<1, 128>>>();

    dim3 g1(T_ / 128, B_, N_);
    disc_mma_kernel<<<g1, 256, SMEM_DISC_BYTES>>>(x, W_enc, b_enc, W_dec, b_dec);

    argmin_kernel<<<1, 32>>>(cidx);

    dim3 g2(T_ / 64, B_);
    mid_kernel<<<g2, 256>>>(x, W_down, b_down);

    dim3 g3(T_ / 128, D_ / 128, B_);
    out_mma_kernel<<<g3, 256, SMEM_OUT_BYTES>>>(x, W_base, b_base, W_up, b_up, out);
}

// round 13
// speedup vs baseline: 5.7798x; 1.3410x over previous
#include <cuda_runtime.h>
#include <cuda_fp16.h>
#include <cstdint>

#define B_ 16
#define T_ 1024
#define D_ 1024
#define H_ 256
#define R_ 64
#define N_ 8

// u32 strides
#define ASTRU 20    // A stage: 128 rows x (32 halves + pad) = 80 B/row
#define BSTRU 68    // B stage: 32 rows x (128 halves + pad) = 272 B/row
#define HSTRU 132   // H: 128 rows x (256 halves + pad)      = 528 B/row

#define SA_SZ (128 * ASTRU)     // 2560 u32
#define SB_SZ (32 * BSTRU)      // 2176 u32
#define OFF_B (4 * SA_SZ)       // 10240
#define OFF_H (OFF_B + 4 * SB_SZ)                   // 18944
#define SMEM_OUT_BYTES  (OFF_H * 4)                 // 75776
#define SMEM_DISC_BYTES ((OFF_H + 128 * HSTRU) * 4) // 143360

// ---------------- scratch ----------------
__device__ float g_losses[N_ * B_];
__device__ int   g_adp[B_];
__device__ __align__(256) __half g_xh [(size_t)B_ * T_ * D_];
__device__ __align__(256) __half g_Weh[(size_t)N_ * D_ * H_];
__device__ __align__(256) __half g_Wdh[(size_t)N_ * H_ * D_];
__device__ __align__(256) __half g_Wbh[(size_t)D_ * D_];
__device__ __align__(256) __half g_Wuh[(size_t)N_ * R_ * D_];
__device__ __align__(256) __half g_midh[(size_t)B_ * T_ * R_];

// ---------------- low-level helpers ----------------
__device__ __forceinline__ uint32_t smem_u32(const void* p) {
    uint32_t a;
    asm("{ .reg .u64 t; cvta.to.shared.u64 t, %1; cvt.u32.u64 %0, t; }" : "=r"(a) : "l"(p));
    return a;
}
#define CP_ASYNC16(s, g) \
    asm volatile("cp.async.cg.shared.global [%0], [%1], 16;" :: "r"(s), "l"((const void*)(g)))
#define CP_COMMIT() asm volatile("cp.async.commit_group;" ::: "memory")
#define CP_WAIT(n)  asm volatile("cp.async.wait_group %0;" :: "n"(n) : "memory")

__device__ __forceinline__ void ldsm4(uint32_t* r, uint32_t addr) {
    asm volatile("ldmatrix.sync.aligned.m8n8.x4.shared.b16 {%0,%1,%2,%3}, [%4];"
                 : "=r"(r[0]), "=r"(r[1]), "=r"(r[2]), "=r"(r[3]) : "r"(addr));
}
__device__ __forceinline__ void ldsm4t(uint32_t* r, uint32_t addr) {
    asm volatile("ldmatrix.sync.aligned.m8n8.x4.trans.shared.b16 {%0,%1,%2,%3}, [%4];"
                 : "=r"(r[0]), "=r"(r[1]), "=r"(r[2]), "=r"(r[3]) : "r"(addr));
}
__device__ __forceinline__ void mma16(float c[4], const uint32_t a[4], const uint32_t b[2]) {
    asm volatile("mma.sync.aligned.m16n8k16.row.col.f32.f16.f16.f32 "
                 "{%0,%1,%2,%3}, {%4,%5,%6,%7}, {%8,%9}, {%0,%1,%2,%3};"
                 : "+f"(c[0]), "+f"(c[1]), "+f"(c[2]), "+f"(c[3])
                 : "r"(a[0]), "r"(a[1]), "r"(a[2]), "r"(a[3]), "r"(b[0]), "r"(b[1]));
}
__device__ __forceinline__ uint32_t packh2(float lo, float hi) {
    __half2 h = __floats2half2_rn(lo, hi);
    return *reinterpret_cast<uint32_t*>(&h);
}

// cp.async slab loaders (256 threads). A: 128 rows x 32 halves.
__device__ __forceinline__ void issueA(uint32_t sA, const __half* g, int ld, int tid) {
#pragma unroll
    for (int l = 0; l < 2; l++) {
        int s = tid + l * 256, row = s >> 2, j = s & 3;
        CP_ASYNC16(sA + (uint32_t)(row * ASTRU + j * 4) * 4, g + (size_t)row * ld + j * 8);
    }
}
// B: 32 rows x 128 halves
__device__ __forceinline__ void issueB(uint32_t sB, const __half* g, int ld, int tid) {
#pragma unroll
    for (int l = 0; l < 2; l++) {
        int s = tid + l * 256, row = s >> 4, j = s & 15;
        CP_ASYNC16(sB + (uint32_t)(row * BSTRU + j * 4) * 4, g + (size_t)row * ld + j * 8);
    }
}

// Proven path (exercised by out base GEMM): A via ldsm4, B via ldsm4t.
__device__ __forceinline__ void frag_compute(uint32_t aBase, uint32_t bBase,
                                             float (*c)[4][4], int lane) {
    const int l16 = lane & 15, hi = lane >> 4;
#pragma unroll
    for (int ks = 0; ks < 2; ks++) {
        uint32_t a[4][4], b4n[2][4];
#pragma unroll
        for (int mt = 0; mt < 4; mt++)
            ldsm4(a[mt], aBase + (uint32_t)((mt * 16 + l16) * 80 + ks * 32 + hi * 16));
#pragma unroll
        for (int np = 0; np < 2; np++)
            ldsm4t(b4n[np], bBase + (uint32_t)((ks * 16 + l16) * 272 + np * 32 + hi * 16));
#pragma unroll
        for (int mt = 0; mt < 4; mt++)
#pragma unroll
            for (int np = 0; np < 2; np++) {
                mma16(c[mt][np * 2 + 0], a[mt], b4n[np] + 0);
                mma16(c[mt][np * 2 + 1], a[mt], b4n[np] + 2);
            }
    }
}

// Disc phase 2: A from H via R9-proven SCALAR u32 reads; B via proven ldsm4t.
__device__ __forceinline__ void frag_compute_h(const uint32_t* __restrict__ Hw, uint32_t bBase,
                                               float (*c)[4][4], int lane, int hcoff) {
    const int lr = lane >> 2, lk = lane & 3;
    const int l16 = lane & 15, hi = lane >> 4;
#pragma unroll
    for (int ks = 0; ks < 2; ks++) {
        uint32_t a[4][4], b4n[2][4];
#pragma unroll
        for (int mt = 0; mt < 4; mt++) {
            const uint32_t* ap = Hw + (mt * 16 + lr) * HSTRU + hcoff + ks * 8 + lk;
            a[mt][0] = ap[0];
            a[mt][1] = ap[8 * HSTRU];
            a[mt][2] = ap[4];
            a[mt][3] = ap[8 * HSTRU + 4];
        }
#pragma unroll
        for (int np = 0; np < 2; np++)
            ldsm4t(b4n[np], bBase + (uint32_t)((ks * 16 + l16) * 272 + np * 32 + hi * 16));
#pragma unroll
        for (int mt = 0; mt < 4; mt++)
#pragma unroll
            for (int np = 0; np < 2; np++) {
                mma16(c[mt][np * 2 + 0], a[mt], b4n[np] + 0);
                mma16(c[mt][np * 2 + 1], a[mt], b4n[np] + 2);
            }
    }
}

// ---------------- tiny kernels ----------------
__global__ void cvt_kernel(const float* __restrict__ src, __half* __restrict__ dst, int n2) {
    int i = blockIdx.x * blockDim.x + threadIdx.x;
    int stride = gridDim.x * blockDim.x;
    for (; i < n2; i += stride) {
        float2 v = reinterpret_cast<const float2*>(src)[i];
        reinterpret_cast<__half2*>(dst)[i] = __floats2half2_rn(v.x, v.y);
    }
}
__global__ void zero_losses_kernel() {
    int i = threadIdx.x;
    if (i < N_ * B_) g_losses[i] = 0.f;
}
__global__ void argmin_kernel(const int* __restrict__ connected_idx) {
    int b = threadIdx.x;
    if (b < B_) {
        float best = g_losses[b];
        int bi = 0;
        for (int n = 1; n < N_; n++) {
            float v = g_losses[n * B_ + b];
            if (v < best) { best = v; bi = n; }
        }
        g_adp[b] = connected_idx[bi];
    }
}

// ---------------- disc loss ----------------
__global__ __launch_bounds__(256)
void disc_mma_kernel(const float* __restrict__ xf,
                     const float* __restrict__ b_enc, const float* __restrict__ b_dec) {
    extern __shared__ uint32_t sm[];
    const uint32_t sb = smem_u32(sm);
    const int tid = threadIdx.x, wid = tid >> 5, lane = tid & 31;
    const int RM = (wid & 1) * 64, CN = (wid >> 1) * 32;
    const int lr = lane >> 2, lk = lane & 3;
    const int n = blockIdx.z, b = blockIdx.y, t0 = blockIdx.x * 128;

    const __half* xb = g_xh + ((size_t)b * T_ + t0) * D_;
    const float* xbf = xf + ((size_t)b * T_ + t0) * D_;
    const __half* We = g_Weh + (size_t)n * D_ * H_;
    const __half* Wd = g_Wdh + (size_t)n * H_ * D_;

    float c[4][4][4];
#pragma unroll
    for (int mt = 0; mt < 4; mt++)
#pragma unroll
        for (int nt = 0; nt < 4; nt++)
#pragma unroll
            for (int i = 0; i < 4; i++) c[mt][nt][i] = 0.f;

    // ===== Phase 1: 64 chunks (nc = q>>5, kc = q&31) =====
    for (int q = 0; q < 2; q++) {
        issueA(sb + (uint32_t)(q & 3) * SA_SZ * 4, xb + (q & 31) * 32, D_, tid);
        issueB(sb + (uint32_t)(OFF_B + (q & 3) * SB_SZ) * 4,
               We + (size_t)(q & 31) * 32 * H_ + (q >> 5) * 128, H_, tid);
        CP_COMMIT();
    }
    for (int q = 0; q < 64; q++) {
        if (q + 2 < 64) {
            int p = q + 2;
            issueA(sb + (uint32_t)(p & 3) * SA_SZ * 4, xb + (p & 31) * 32, D_, tid);
            issueB(sb + (uint32_t)(OFF_B + (p & 3) * SB_SZ) * 4,
                   We + (size_t)(p & 31) * 32 * H_ + (p >> 5) * 128, H_, tid);
            CP_COMMIT();
        }
        if (q + 2 < 64) { CP_WAIT(2); } else if (q + 1 < 64) { CP_WAIT(1); } else { CP_WAIT(0); }
        __syncthreads();
        frag_compute(sb + (uint32_t)(q & 3) * SA_SZ * 4 + RM * 80,
                     sb + (uint32_t)(OFF_B + (q & 3) * SB_SZ) * 4 + CN * 2, c, lane);
        if ((q & 31) == 31) {
            int nc = q >> 5;
#pragma unroll
            for (int mt = 0; mt < 4; mt++) {
                int r = RM + mt * 16 + lr;
#pragma unroll
                for (int nt = 0; nt < 4; nt++) {
                    int col = nc * 128 + CN + nt * 8 + lk * 2;
                    float be0 = __ldg(b_enc + n * H_ + col);
                    float be1 = __ldg(b_enc + n * H_ + col + 1);
                    float v0 = c[mt][nt][0] + be0, v1 = c[mt][nt][1] + be1;
                    float v2 = c[mt][nt][2] + be0, v3 = c[mt][nt][3] + be1;
                    sm[OFF_H + r * HSTRU + (col >> 1)] =
                        packh2(v0 > 0.f ? v0 : 0.f, v1 > 0.f ? v1 : 0.f);
                    sm[OFF_H + (r + 8) * HSTRU + (col >> 1)] =
                        packh2(v2 > 0.f ? v2 : 0.f, v3 > 0.f ? v3 : 0.f);
                    c[mt][nt][0] = c[mt][nt][1] = c[mt][nt][2] = c[mt][nt][3] = 0.f;
                }
            }
        }
    }

    // ===== Phase 2: 64 chunks (dc = q>>3 in 0..7, hc = q&7), A = H (scalar reads) =====
    float ss = 0.f;
    for (int q = 0; q < 2; q++) {
        issueB(sb + (uint32_t)(OFF_B + (q & 3) * SB_SZ) * 4,
               Wd + (size_t)(q & 7) * 32 * D_ + (q >> 3) * 128, D_, tid);
        CP_COMMIT();
    }
    for (int q = 0; q < 64; q++) {
        if (q + 2 < 64) {
            int p = q + 2;
            issueB(sb + (uint32_t)(OFF_B + (p & 3) * SB_SZ) * 4,
                   Wd + (size_t)(p & 7) * 32 * D_ + (p >> 3) * 128, D_, tid);
            CP_COMMIT();
        }
        if (q + 2 < 64) { CP_WAIT(2); } else if (q + 1 < 64) { CP_WAIT(1); } else { CP_WAIT(0); }
        __syncthreads();
        frag_compute_h(sm + OFF_H + RM * HSTRU,
                       sb + (uint32_t)(OFF_B + (q & 3) * SB_SZ) * 4 + CN * 2,
                       c, lane, (q & 7) * 16);
        if ((q & 7) == 7) {
            int dc = q >> 3;
#pragma unroll
            for (int mt = 0; mt < 4; mt++) {
                int r = RM + mt * 16 + lr;
#pragma unroll
                for (int nt = 0; nt < 4; nt++) {
                    int col = dc * 128 + CN + nt * 8 + lk * 2;
                    float bd0 = __ldg(b_dec + n * D_ + col);
                    float bd1 = __ldg(b_dec + n * D_ + col + 1);
                    float2 x0 = *reinterpret_cast<const float2*>(xbf + (size_t)r * D_ + col);
                    float2 x1 = *reinterpret_cast<const float2*>(xbf + (size_t)(r + 8) * D_ + col);
                    float e0 = c[mt][nt][0] + bd0 - x0.x;
                    float e1 = c[mt][nt][1] + bd1 - x0.y;
                    float e2 = c[mt][nt][2] + bd0 - x1.x;
                    float e3 = c[mt][nt][3] + bd1 - x1.y;
                    ss = fmaf(e0, e0, ss); ss = fmaf(e1, e1, ss);
                    ss = fmaf(e2, e2, ss); ss = fmaf(e3, e3, ss);
                    c[mt][nt][0] = c[mt][nt][1] = c[mt][nt][2] = c[mt][nt][3] = 0.f;
                }
            }
        }
    }

#pragma unroll
    for (int o = 16; o > 0; o >>= 1)
        ss += __shfl_down_sync(0xffffffffu, ss, o);
    __shared__ float red[8];
    if (lane == 0) red[wid] = ss;
    __syncthreads();
    if (tid == 0) {
        float s = 0.f;
#pragma unroll
        for (int i = 0; i < 8; i++) s += red[i];
        atomicAdd(&g_losses[n * B_ + b], s);
    }
}

// ---------------- mid: R9-proven SIMT fp32, stores fp16 to g_midh ----------------
__global__ void mid_kernel(const float* __restrict__ x,
                           const float* __restrict__ W_down,
                           const float* __restrict__ b_down) {
    __shared__ float xs[64 * 32];
    __shared__ float wd[32 * R_];
    const int b = blockIdx.y, t0 = blockIdx.x * 64;
    const int tid = threadIdx.x;
    const int tr = tid >> 4, tc = tid & 15;
    const int a = g_adp[b];
    const float* xb = x + ((size_t)b * T_ + t0) * D_;
    const float* Wd = W_down + (size_t)a * D_ * R_;

    float acc[4][4];
#pragma unroll
    for (int i = 0; i < 4; i++)
#pragma unroll
        for (int j = 0; j < 4; j++) acc[i][j] = 0.f;

    for (int k0 = 0; k0 < D_; k0 += 32) {
        __syncthreads();
#pragma unroll
        for (int l = 0; l < 8; l++) {
            int idx = tid + l * 256;
            xs[idx] = xb[(size_t)(idx >> 5) * D_ + k0 + (idx & 31)];
        }
#pragma unroll
        for (int l = 0; l < 8; l++) {
            int idx = tid + l * 256;
            wd[idx] = Wd[(size_t)(k0 + (idx >> 6)) * R_ + (idx & 63)];
        }
        __syncthreads();
#pragma unroll
        for (int kk = 0; kk < 32; kk++) {
            float av[4], wv[4];
#pragma unroll
            for (int i = 0; i < 4; i++) av[i] = xs[(tr * 4 + i) * 32 + kk];
#pragma unroll
            for (int j = 0; j < 4; j++) wv[j] = wd[kk * R_ + tc + 16 * j];
#pragma unroll
            for (int i = 0; i < 4; i++)
#pragma unroll
                for (int j = 0; j < 4; j++)
                    acc[i][j] = fmaf(av[i], wv[j], acc[i][j]);
        }
    }
#pragma unroll
    for (int i = 0; i < 4; i++) {
        int rr = tr * 4 + i;
#pragma unroll
        for (int j = 0; j < 4; j++) {
            int col = tc + 16 * j;
            float v = acc[i][j] + b_down[a * R_ + col];
            g_midh[((size_t)b * T_ + t0 + rr) * R_ + col] = __float2half(v > 0.f ? v : 0.f);
        }
    }
}

// ---------------- out = x@W_base + mid@W_up + biases ----------------
__global__ __launch_bounds__(256)
void out_mma_kernel(const float* __restrict__ b_base, const float* __restrict__ b_up,
                    float* __restrict__ out) {
    extern __shared__ uint32_t sm[];
    const uint32_t sb = smem_u32(sm);
    const int tid = threadIdx.x, wid = tid >> 5, lane = tid & 31;
    const int RM = (wid & 1) * 64, CN = (wid >> 1) * 32;
    const int lr = lane >> 2, lk = lane & 3;
    const int b = blockIdx.z, e0 = blockIdx.y * 128, t0 = blockIdx.x * 128;
    const int a = g_adp[b];

    const __half* xb = g_xh + ((size_t)b * T_ + t0) * D_;
    const __half* mb = g_midh + ((size_t)b * T_ + t0) * R_;
    const __half* Wb = g_Wbh;
    const __half* Wu = g_Wuh + (size_t)a * R_ * D_;

    float c[4][4][4];
#pragma unroll
    for (int mt = 0; mt < 4; mt++)
#pragma unroll
        for (int nt = 0; nt < 4; nt++)
#pragma unroll
            for (int i = 0; i < 4; i++) c[mt][nt][i] = 0.f;

    const int NC = 34;
    for (int q = 0; q < 2; q++) {
        issueA(sb + (uint32_t)(q & 3) * SA_SZ * 4, xb + q * 32, D_, tid);
        issueB(sb + (uint32_t)(OFF_B + (q & 3) * SB_SZ) * 4, Wb + (size_t)q * 32 * D_ + e0, D_, tid);
        CP_COMMIT();
    }
    for (int q = 0; q < NC; q++) {
        if (q + 2 < NC) {
            int p = q + 2;
            if (p < 32) {
                issueA(sb + (uint32_t)(p & 3) * SA_SZ * 4, xb + p * 32, D_, tid);
                issueB(sb + (uint32_t)(OFF_B + (p & 3) * SB_SZ) * 4,
                       Wb + (size_t)p * 32 * D_ + e0, D_, tid);
            } else {
                issueA(sb + (uint32_t)(p & 3) * SA_SZ * 4, mb + (p - 32) * 32, R_, tid);
                issueB(sb + (uint32_t)(OFF_B + (p & 3) * SB_SZ) * 4,
                       Wu + (size_t)(p - 32) * 32 * D_ + e0, D_, tid);
            }
            CP_COMMIT();
        }
        if (q + 2 < NC) { CP_WAIT(2); } else if (q + 1 < NC) { CP_WAIT(1); } else { CP_WAIT(0); }
        __syncthreads();
        frag_compute(sb + (uint32_t)(q & 3) * SA_SZ * 4 + RM * 80,
                     sb + (uint32_t)(OFF_B + (q & 3) * SB_SZ) * 4 + CN * 2, c, lane);
    }

#pragma unroll
    for (int mt = 0; mt < 4; mt++) {
        int r = RM + mt * 16 + lr;
#pragma unroll
        for (int nt = 0; nt < 4; nt++) {
            int col = e0 + CN + nt * 8 + lk * 2;
            float bb0 = __ldg(b_base + col) + __ldg(b_up + a * D_ + col);
            float bb1 = __ldg(b_base + col + 1) + __ldg(b_up + a * D_ + col + 1);
            float2 v0 = make_float2(c[mt][nt][0] + bb0, c[mt][nt][1] + bb1);
            float2 v1 = make_float2(c[mt][nt][2] + bb0, c[mt][nt][3] + bb1);
            *reinterpret_cast<float2*>(out + ((size_t)b * T_ + t0 + r) * D_ + col) = v0;
            *reinterpret_cast<float2*>(out + ((size_t)b * T_ + t0 + r + 8) * D_ + col) = v1;
        }
    }
}

// ---------------------------------------------------------------------------
extern "C" void kernel_launch(void* const* d_in, const int* in_sizes, int n_in,
                              void* d_out, int out_size) {
    const float* x      = (const float*)d_in[0];
    const float* W_base = (const float*)d_in[1];
    const float* b_base = (const float*)d_in[2];
    const float* W_enc  = (const float*)d_in[3];
    const float* b_enc  = (const float*)d_in[4];
    const float* W_dec  = (const float*)d_in[5];
    const float* b_dec  = (const float*)d_in[6];
    const float* W_down = (const float*)d_in[7];
    const float* b_down = (const float*)d_in[8];
    const float* W_up   = (const float*)d_in[9];
    const float* b_up   = (const float*)d_in[10];
    const int*   cidx   = (const int*)d_in[11];
    float* out = (float*)d_out;

    static __half *p_xh = nullptr, *p_We, *p_Wd, *p_Wb, *p_Wu;
    if (!p_xh) {
        cudaGetSymbolAddress((void**)&p_xh, g_xh);
        cudaGetSymbolAddress((void**)&p_We, g_Weh);
        cudaGetSymbolAddress((void**)&p_Wd, g_Wdh);
        cudaGetSymbolAddress((void**)&p_Wb, g_Wbh);
        cudaGetSymbolAddress((void**)&p_Wu, g_Wuh);
        cudaFuncSetAttribute(disc_mma_kernel,
                             cudaFuncAttributeMaxDynamicSharedMemorySize, SMEM_DISC_BYTES);
        cudaFuncSetAttribute(out_mma_kernel,
                             cudaFuncAttributeMaxDynamicSharedMemorySize, SMEM_OUT_BYTES);
    }

    cvt_kernel<<<2048, 256>>>(x, p_xh, B_ * T_ * D_ / 2);
    cvt_kernel<<<512, 256>>>(W_enc, p_We, N_ * D_ * H_ / 2);
    cvt_kernel<<<512, 256>>>(W_dec, p_Wd, N_ * H_ * D_ / 2);
    cvt_kernel<<<256, 256>>>(W_base, p_Wb, D_ * D_ / 2);
    cvt_kernel<<<128, 256>>>(W_up, p_Wu, N_ * R_ * D_ / 2);
    zero_losses_kernel<<<1, 128>>>();

    dim3 g1(T_ / 128, B_, N_);
    disc_mma_kernel<<<g1, 256, SMEM_DISC_BYTES>>>(x, b_enc, b_dec);

    argmin_kernel<<<1, 32>>>(cidx);

    dim3 g2(T_ / 64, B_);
    mid_kernel<<<g2, 256>>>(x, W_down, b_down);

    dim3 g3(T_ / 128, D_ / 128, B_);
    out_mma_kernel<<<g3, 256, SMEM_OUT_BYTES>>>(b_base, b_up, out);
}

// round 14
// speedup vs baseline: 6.2540x; 1.0820x over previous
#include <cuda_runtime.h>
#include <cuda_fp16.h>
#include <cstdint>

#define B_ 16
#define T_ 1024
#define D_ 1024
#define H_ 256
#define R_ 64
#define N_ 8

// u32 strides
#define ASTRU 20    // A stage: 128 rows x (32 halves + pad) = 80 B/row
#define BSTRU 68    // B stage: 32 rows x (128 halves + pad) = 272 B/row
#define MSTRU 36    // mid B stage: 32 rows x (64 halves + pad) = 144 B/row
#define HSTRU 132   // H: 128 rows x (256 halves + pad)      = 528 B/row

#define SA_SZ (128 * ASTRU)     // 2560 u32
#define SB_SZ (32 * BSTRU)      // 2176 u32
#define SM_SZ (32 * MSTRU)      // 1152 u32
#define OFF_B (4 * SA_SZ)       // 10240
#define OFF_H (OFF_B + 4 * SB_SZ)                   // 18944
#define SMEM_OUT_BYTES  (OFF_H * 4)                 // 75776
#define SMEM_DISC_BYTES ((OFF_H + 128 * HSTRU) * 4) // 143360
#define SMEM_MID_BYTES  ((4 * SA_SZ + 4 * SM_SZ) * 4) // 59392

// ---------------- scratch ----------------
__device__ float g_losses[N_ * B_];
__device__ int   g_adp[B_];
__device__ __align__(256) __half g_xh [(size_t)B_ * T_ * D_];
__device__ __align__(256) __half g_Weh[(size_t)N_ * D_ * H_];
__device__ __align__(256) __half g_Wdh[(size_t)N_ * H_ * D_];
__device__ __align__(256) __half g_Wbh[(size_t)D_ * D_];
__device__ __align__(256) __half g_Wnh[(size_t)N_ * D_ * R_];
__device__ __align__(256) __half g_Wuh[(size_t)N_ * R_ * D_];
__device__ __align__(256) __half g_midh[(size_t)B_ * T_ * R_];

// ---------------- low-level helpers ----------------
__device__ __forceinline__ uint32_t smem_u32(const void* p) {
    uint32_t a;
    asm("{ .reg .u64 t; cvta.to.shared.u64 t, %1; cvt.u32.u64 %0, t; }" : "=r"(a) : "l"(p));
    return a;
}
#define CP_ASYNC16(s, g) \
    asm volatile("cp.async.cg.shared.global [%0], [%1], 16;" :: "r"(s), "l"((const void*)(g)))
#define CP_COMMIT() asm volatile("cp.async.commit_group;" ::: "memory")
#define CP_WAIT(n)  asm volatile("cp.async.wait_group %0;" :: "n"(n) : "memory")

__device__ __forceinline__ void ldsm4(uint32_t* r, uint32_t addr) {
    asm volatile("ldmatrix.sync.aligned.m8n8.x4.shared.b16 {%0,%1,%2,%3}, [%4];"
                 : "=r"(r[0]), "=r"(r[1]), "=r"(r[2]), "=r"(r[3]) : "r"(addr));
}
__device__ __forceinline__ void ldsm4t(uint32_t* r, uint32_t addr) {
    asm volatile("ldmatrix.sync.aligned.m8n8.x4.trans.shared.b16 {%0,%1,%2,%3}, [%4];"
                 : "=r"(r[0]), "=r"(r[1]), "=r"(r[2]), "=r"(r[3]) : "r"(addr));
}
__device__ __forceinline__ void mma16(float c[4], const uint32_t a[4], const uint32_t b[2]) {
    asm volatile("mma.sync.aligned.m16n8k16.row.col.f32.f16.f16.f32 "
                 "{%0,%1,%2,%3}, {%4,%5,%6,%7}, {%8,%9}, {%0,%1,%2,%3};"
                 : "+f"(c[0]), "+f"(c[1]), "+f"(c[2]), "+f"(c[3])
                 : "r"(a[0]), "r"(a[1]), "r"(a[2]), "r"(a[3]), "r"(b[0]), "r"(b[1]));
}
__device__ __forceinline__ uint32_t packh2(float lo, float hi) {
    __half2 h = __floats2half2_rn(lo, hi);
    return *reinterpret_cast<uint32_t*>(&h);
}

// cp.async slab loaders (256 threads). A: 128 rows x 32 halves.
__device__ __forceinline__ void issueA(uint32_t sA, const __half* g, int ld, int tid) {
#pragma unroll
    for (int l = 0; l < 2; l++) {
        int s = tid + l * 256, row = s >> 2, j = s & 3;
        CP_ASYNC16(sA + (uint32_t)(row * ASTRU + j * 4) * 4, g + (size_t)row * ld + j * 8);
    }
}
// B: 32 rows x 128 halves
__device__ __forceinline__ void issueB(uint32_t sB, const __half* g, int ld, int tid) {
#pragma unroll
    for (int l = 0; l < 2; l++) {
        int s = tid + l * 256, row = s >> 4, j = s & 15;
        CP_ASYNC16(sB + (uint32_t)(row * BSTRU + j * 4) * 4, g + (size_t)row * ld + j * 8);
    }
}
// mid B: 32 rows x 64 halves (128 B/row)
__device__ __forceinline__ void issueBm(uint32_t sB, const __half* g, int tid) {
    int row = tid >> 3, j = tid & 7;
    CP_ASYNC16(sB + (uint32_t)(row * MSTRU + j * 4) * 4, g + (size_t)row * R_ + j * 8);
}

// Proven path: A via ldsm4, B via ldsm4t (bstr bytes).
template<int NP>
__device__ __forceinline__ void frag_compute(uint32_t aBase, uint32_t bBase, int bstr,
                                             float (*c)[2 * NP][4], int lane) {
    const int l16 = lane & 15, hi = lane >> 4;
#pragma unroll
    for (int ks = 0; ks < 2; ks++) {
        uint32_t a[4][4], b4n[NP][4];
#pragma unroll
        for (int mt = 0; mt < 4; mt++)
            ldsm4(a[mt], aBase + (uint32_t)((mt * 16 + l16) * 80 + ks * 32 + hi * 16));
#pragma unroll
        for (int np = 0; np < NP; np++)
            ldsm4t(b4n[np], bBase + (uint32_t)((ks * 16 + l16) * bstr + np * 32 + hi * 16));
#pragma unroll
        for (int mt = 0; mt < 4; mt++)
#pragma unroll
            for (int np = 0; np < NP; np++) {
                mma16(c[mt][np * 2 + 0], a[mt], b4n[np] + 0);
                mma16(c[mt][np * 2 + 1], a[mt], b4n[np] + 2);
            }
    }
}

// Disc phase 2: A from H via proven SCALAR u32 reads; B via proven ldsm4t.
__device__ __forceinline__ void frag_compute_h(const uint32_t* __restrict__ Hw, uint32_t bBase,
                                               float (*c)[4][4], int lane, int hcoff) {
    const int lr = lane >> 2, lk = lane & 3;
    const int l16 = lane & 15, hi = lane >> 4;
#pragma unroll
    for (int ks = 0; ks < 2; ks++) {
        uint32_t a[4][4], b4n[2][4];
#pragma unroll
        for (int mt = 0; mt < 4; mt++) {
            const uint32_t* ap = Hw + (mt * 16 + lr) * HSTRU + hcoff + ks * 8 + lk;
            a[mt][0] = ap[0];
            a[mt][1] = ap[8 * HSTRU];
            a[mt][2] = ap[4];
            a[mt][3] = ap[8 * HSTRU + 4];
        }
#pragma unroll
        for (int np = 0; np < 2; np++)
            ldsm4t(b4n[np], bBase + (uint32_t)((ks * 16 + l16) * 272 + np * 32 + hi * 16));
#pragma unroll
        for (int mt = 0; mt < 4; mt++)
#pragma unroll
            for (int np = 0; np < 2; np++) {
                mma16(c[mt][np * 2 + 0], a[mt], b4n[np] + 0);
                mma16(c[mt][np * 2 + 1], a[mt], b4n[np] + 2);
            }
    }
}

// ---------------- tiny kernels ----------------
__global__ void cvt_kernel(const float* __restrict__ src, __half* __restrict__ dst, int n2) {
    int i = blockIdx.x * blockDim.x + threadIdx.x;
    int stride = gridDim.x * blockDim.x;
    for (; i < n2; i += stride) {
        float2 v = reinterpret_cast<const float2*>(src)[i];
        reinterpret_cast<__half2*>(dst)[i] = __floats2half2_rn(v.x, v.y);
    }
}
__global__ void zero_losses_kernel() {
    int i = threadIdx.x;
    if (i < N_ * B_) g_losses[i] = 0.f;
}
__global__ void argmin_kernel(const int* __restrict__ connected_idx) {
    int b = threadIdx.x;
    if (b < B_) {
        float best = g_losses[b];
        int bi = 0;
        for (int n = 1; n < N_; n++) {
            float v = g_losses[n * B_ + b];
            if (v < best) { best = v; bi = n; }
        }
        g_adp[b] = connected_idx[bi];
    }
}

// ---------------- disc loss ----------------
__global__ __launch_bounds__(256)
void disc_mma_kernel(const float* __restrict__ xf,
                     const float* __restrict__ b_enc, const float* __restrict__ b_dec) {
    extern __shared__ uint32_t sm[];
    const uint32_t sb = smem_u32(sm);
    const int tid = threadIdx.x, wid = tid >> 5, lane = tid & 31;
    const int RM = (wid & 1) * 64, CN = (wid >> 1) * 32;
    const int lr = lane >> 2, lk = lane & 3;
    const int n = blockIdx.z, b = blockIdx.y, t0 = blockIdx.x * 128;

    const __half* xb = g_xh + ((size_t)b * T_ + t0) * D_;
    const float* xbf = xf + ((size_t)b * T_ + t0) * D_;
    const __half* We = g_Weh + (size_t)n * D_ * H_;
    const __half* Wd = g_Wdh + (size_t)n * H_ * D_;

    float c[4][4][4];
#pragma unroll
    for (int mt = 0; mt < 4; mt++)
#pragma unroll
        for (int nt = 0; nt < 4; nt++)
#pragma unroll
            for (int i = 0; i < 4; i++) c[mt][nt][i] = 0.f;

    // ===== Phase 1: 64 chunks (nc = q>>5, kc = q&31) =====
    for (int q = 0; q < 2; q++) {
        issueA(sb + (uint32_t)(q & 3) * SA_SZ * 4, xb + (q & 31) * 32, D_, tid);
        issueB(sb + (uint32_t)(OFF_B + (q & 3) * SB_SZ) * 4,
               We + (size_t)(q & 31) * 32 * H_ + (q >> 5) * 128, H_, tid);
        CP_COMMIT();
    }
    for (int q = 0; q < 64; q++) {
        if (q + 2 < 64) {
            int p = q + 2;
            issueA(sb + (uint32_t)(p & 3) * SA_SZ * 4, xb + (p & 31) * 32, D_, tid);
            issueB(sb + (uint32_t)(OFF_B + (p & 3) * SB_SZ) * 4,
                   We + (size_t)(p & 31) * 32 * H_ + (p >> 5) * 128, H_, tid);
            CP_COMMIT();
        }
        if (q + 2 < 64) { CP_WAIT(2); } else if (q + 1 < 64) { CP_WAIT(1); } else { CP_WAIT(0); }
        __syncthreads();
        frag_compute<2>(sb + (uint32_t)(q & 3) * SA_SZ * 4 + RM * 80,
                        sb + (uint32_t)(OFF_B + (q & 3) * SB_SZ) * 4 + CN * 2, 272, c, lane);
        if ((q & 31) == 31) {
            int nc = q >> 5;
#pragma unroll
            for (int mt = 0; mt < 4; mt++) {
                int r = RM + mt * 16 + lr;
#pragma unroll
                for (int nt = 0; nt < 4; nt++) {
                    int col = nc * 128 + CN + nt * 8 + lk * 2;
                    float be0 = __ldg(b_enc + n * H_ + col);
                    float be1 = __ldg(b_enc + n * H_ + col + 1);
                    float v0 = c[mt][nt][0] + be0, v1 = c[mt][nt][1] + be1;
                    float v2 = c[mt][nt][2] + be0, v3 = c[mt][nt][3] + be1;
                    sm[OFF_H + r * HSTRU + (col >> 1)] =
                        packh2(v0 > 0.f ? v0 : 0.f, v1 > 0.f ? v1 : 0.f);
                    sm[OFF_H + (r + 8) * HSTRU + (col >> 1)] =
                        packh2(v2 > 0.f ? v2 : 0.f, v3 > 0.f ? v3 : 0.f);
                    c[mt][nt][0] = c[mt][nt][1] = c[mt][nt][2] = c[mt][nt][3] = 0.f;
                }
            }
        }
    }

    // ===== Phase 2: 64 chunks (dc = q>>3 in 0..7, hc = q&7), A = H (scalar reads) =====
    float ss = 0.f;
    for (int q = 0; q < 2; q++) {
        issueB(sb + (uint32_t)(OFF_B + (q & 3) * SB_SZ) * 4,
               Wd + (size_t)(q & 7) * 32 * D_ + (q >> 3) * 128, D_, tid);
        CP_COMMIT();
    }
    for (int q = 0; q < 64; q++) {
        if (q + 2 < 64) {
            int p = q + 2;
            issueB(sb + (uint32_t)(OFF_B + (p & 3) * SB_SZ) * 4,
                   Wd + (size_t)(p & 7) * 32 * D_ + (p >> 3) * 128, D_, tid);
            CP_COMMIT();
        }
        if (q + 2 < 64) { CP_WAIT(2); } else if (q + 1 < 64) { CP_WAIT(1); } else { CP_WAIT(0); }
        __syncthreads();
        frag_compute_h(sm + OFF_H + RM * HSTRU,
                       sb + (uint32_t)(OFF_B + (q & 3) * SB_SZ) * 4 + CN * 2,
                       c, lane, (q & 7) * 16);
        if ((q & 7) == 7) {
            int dc = q >> 3;
#pragma unroll
            for (int mt = 0; mt < 4; mt++) {
                int r = RM + mt * 16 + lr;
#pragma unroll
                for (int nt = 0; nt < 4; nt++) {
                    int col = dc * 128 + CN + nt * 8 + lk * 2;
                    float bd0 = __ldg(b_dec + n * D_ + col);
                    float bd1 = __ldg(b_dec + n * D_ + col + 1);
                    float2 x0 = *reinterpret_cast<const float2*>(xbf + (size_t)r * D_ + col);
                    float2 x1 = *reinterpret_cast<const float2*>(xbf + (size_t)(r + 8) * D_ + col);
                    float e0 = c[mt][nt][0] + bd0 - x0.x;
                    float e1 = c[mt][nt][1] + bd1 - x0.y;
                    float e2 = c[mt][nt][2] + bd0 - x1.x;
                    float e3 = c[mt][nt][3] + bd1 - x1.y;
                    ss = fmaf(e0, e0, ss); ss = fmaf(e1, e1, ss);
                    ss = fmaf(e2, e2, ss); ss = fmaf(e3, e3, ss);
                    c[mt][nt][0] = c[mt][nt][1] = c[mt][nt][2] = c[mt][nt][3] = 0.f;
                }
            }
        }
    }

#pragma unroll
    for (int o = 16; o > 0; o >>= 1)
        ss += __shfl_down_sync(0xffffffffu, ss, o);
    __shared__ float red[8];
    if (lane == 0) red[wid] = ss;
    __syncthreads();
    if (tid == 0) {
        float s = 0.f;
#pragma unroll
        for (int i = 0; i < 8; i++) s += red[i];
        atomicAdd(&g_losses[n * B_ + b], s);
    }
}

// ---------------- mid = relu(x @ W_down[adp] + b_down) -> g_midh (fp16 MMA) ----------------
__global__ __launch_bounds__(256)
void mid_mma_kernel(const float* __restrict__ b_down) {
    extern __shared__ uint32_t sm[];
    const uint32_t sb = smem_u32(sm);
    const int tid = threadIdx.x, wid = tid >> 5, lane = tid & 31;
    const int RM = (wid & 1) * 64, CN = (wid >> 1) * 16;
    const int lr = lane >> 2, lk = lane & 3;
    const int b = blockIdx.y, t0 = blockIdx.x * 128;
    const int a = g_adp[b];

    const __half* xb = g_xh + ((size_t)b * T_ + t0) * D_;
    const __half* Wn = g_Wnh + (size_t)a * D_ * R_;

    float c[4][2][4];
#pragma unroll
    for (int mt = 0; mt < 4; mt++)
#pragma unroll
        for (int nt = 0; nt < 2; nt++)
#pragma unroll
            for (int i = 0; i < 4; i++) c[mt][nt][i] = 0.f;

    for (int q = 0; q < 2; q++) {
        issueA(sb + (uint32_t)(q & 3) * SA_SZ * 4, xb + q * 32, D_, tid);
        issueBm(sb + (uint32_t)(4 * SA_SZ + (q & 3) * SM_SZ) * 4, Wn + (size_t)q * 32 * R_, tid);
        CP_COMMIT();
    }
    for (int q = 0; q < 32; q++) {
        if (q + 2 < 32) {
            int p = q + 2;
            issueA(sb + (uint32_t)(p & 3) * SA_SZ * 4, xb + p * 32, D_, tid);
            issueBm(sb + (uint32_t)(4 * SA_SZ + (p & 3) * SM_SZ) * 4, Wn + (size_t)p * 32 * R_, tid);
            CP_COMMIT();
        }
        if (q + 2 < 32) { CP_WAIT(2); } else if (q + 1 < 32) { CP_WAIT(1); } else { CP_WAIT(0); }
        __syncthreads();
        frag_compute<1>(sb + (uint32_t)(q & 3) * SA_SZ * 4 + RM * 80,
                        sb + (uint32_t)(4 * SA_SZ + (q & 3) * SM_SZ) * 4 + CN * 2, 144, c, lane);
    }

#pragma unroll
    for (int mt = 0; mt < 4; mt++) {
        int r = RM + mt * 16 + lr;
#pragma unroll
        for (int nt = 0; nt < 2; nt++) {
            int col = CN + nt * 8 + lk * 2;
            float bd0 = __ldg(b_down + a * R_ + col);
            float bd1 = __ldg(b_down + a * R_ + col + 1);
            float v0 = c[mt][nt][0] + bd0, v1 = c[mt][nt][1] + bd1;
            float v2 = c[mt][nt][2] + bd0, v3 = c[mt][nt][3] + bd1;
            *reinterpret_cast<uint32_t*>(g_midh + ((size_t)b * T_ + t0 + r) * R_ + col) =
                packh2(v0 > 0.f ? v0 : 0.f, v1 > 0.f ? v1 : 0.f);
            *reinterpret_cast<uint32_t*>(g_midh + ((size_t)b * T_ + t0 + r + 8) * R_ + col) =
                packh2(v2 > 0.f ? v2 : 0.f, v3 > 0.f ? v3 : 0.f);
        }
    }
}

// ---------------- out = x@W_base + mid@W_up + biases ----------------
__global__ __launch_bounds__(256)
void out_mma_kernel(const float* __restrict__ b_base, const float* __restrict__ b_up,
                    float* __restrict__ out) {
    extern __shared__ uint32_t sm[];
    const uint32_t sb = smem_u32(sm);
    const int tid = threadIdx.x, wid = tid >> 5, lane = tid & 31;
    const int RM = (wid & 1) * 64, CN = (wid >> 1) * 32;
    const int lr = lane >> 2, lk = lane & 3;
    const int b = blockIdx.z, e0 = blockIdx.y * 128, t0 = blockIdx.x * 128;
    const int a = g_adp[b];

    const __half* xb = g_xh + ((size_t)b * T_ + t0) * D_;
    const __half* mb = g_midh + ((size_t)b * T_ + t0) * R_;
    const __half* Wb = g_Wbh;
    const __half* Wu = g_Wuh + (size_t)a * R_ * D_;

    float c[4][4][4];
#pragma unroll
    for (int mt = 0; mt < 4; mt++)
#pragma unroll
        for (int nt = 0; nt < 4; nt++)
#pragma unroll
            for (int i = 0; i < 4; i++) c[mt][nt][i] = 0.f;

    const int NC = 34;
    for (int q = 0; q < 2; q++) {
        issueA(sb + (uint32_t)(q & 3) * SA_SZ * 4, xb + q * 32, D_, tid);
        issueB(sb + (uint32_t)(OFF_B + (q & 3) * SB_SZ) * 4, Wb + (size_t)q * 32 * D_ + e0, D_, tid);
        CP_COMMIT();
    }
    for (int q = 0; q < NC; q++) {
        if (q + 2 < NC) {
            int p = q + 2;
            if (p < 32) {
                issueA(sb + (uint32_t)(p & 3) * SA_SZ * 4, xb + p * 32, D_, tid);
                issueB(sb + (uint32_t)(OFF_B + (p & 3) * SB_SZ) * 4,
                       Wb + (size_t)p * 32 * D_ + e0, D_, tid);
            } else {
                issueA(sb + (uint32_t)(p & 3) * SA_SZ * 4, mb + (p - 32) * 32, R_, tid);
                issueB(sb + (uint32_t)(OFF_B + (p & 3) * SB_SZ) * 4,
                       Wu + (size_t)(p - 32) * 32 * D_ + e0, D_, tid);
            }
            CP_COMMIT();
        }
        if (q + 2 < NC) { CP_WAIT(2); } else if (q + 1 < NC) { CP_WAIT(1); } else { CP_WAIT(0); }
        __syncthreads();
        frag_compute<2>(sb + (uint32_t)(q & 3) * SA_SZ * 4 + RM * 80,
                        sb + (uint32_t)(OFF_B + (q & 3) * SB_SZ) * 4 + CN * 2, 272, c, lane);
    }

#pragma unroll
    for (int mt = 0; mt < 4; mt++) {
        int r = RM + mt * 16 + lr;
#pragma unroll
        for (int nt = 0; nt < 4; nt++) {
            int col = e0 + CN + nt * 8 + lk * 2;
            float bb0 = __ldg(b_base + col) + __ldg(b_up + a * D_ + col);
            float bb1 = __ldg(b_base + col + 1) + __ldg(b_up + a * D_ + col + 1);
            float2 v0 = make_float2(c[mt][nt][0] + bb0, c[mt][nt][1] + bb1);
            float2 v1 = make_float2(c[mt][nt][2] + bb0, c[mt][nt][3] + bb1);
            *reinterpret_cast<float2*>(out + ((size_t)b * T_ + t0 + r) * D_ + col) = v0;
            *reinterpret_cast<float2*>(out + ((size_t)b * T_ + t0 + r + 8) * D_ + col) = v1;
        }
    }
}

// ---------------------------------------------------------------------------
extern "C" void kernel_launch(void* const* d_in, const int* in_sizes, int n_in,
                              void* d_out, int out_size) {
    const float* x      = (const float*)d_in[0];
    const float* W_base = (const float*)d_in[1];
    const float* b_base = (const float*)d_in[2];
    const float* W_enc  = (const float*)d_in[3];
    const float* b_enc  = (const float*)d_in[4];
    const float* W_dec  = (const float*)d_in[5];
    const float* b_dec  = (const float*)d_in[6];
    const float* W_down = (const float*)d_in[7];
    const float* b_down = (const float*)d_in[8];
    const float* W_up   = (const float*)d_in[9];
    const float* b_up   = (const float*)d_in[10];
    const int*   cidx   = (const int*)d_in[11];
    float* out = (float*)d_out;

    static __half *p_xh = nullptr, *p_We, *p_Wd, *p_Wb, *p_Wn, *p_Wu;
    if (!p_xh) {
        cudaGetSymbolAddress((void**)&p_xh, g_xh);
        cudaGetSymbolAddress((void**)&p_We, g_Weh);
        cudaGetSymbolAddress((void**)&p_Wd, g_Wdh);
        cudaGetSymbolAddress((void**)&p_Wb, g_Wbh);
        cudaGetSymbolAddress((void**)&p_Wn, g_Wnh);
        cudaGetSymbolAddress((void**)&p_Wu, g_Wuh);
        cudaFuncSetAttribute(disc_mma_kernel,
                             cudaFuncAttributeMaxDynamicSharedMemorySize, SMEM_DISC_BYTES);
        cudaFuncSetAttribute(out_mma_kernel,
                             cudaFuncAttributeMaxDynamicSharedMemorySize, SMEM_OUT_BYTES);
        cudaFuncSetAttribute(mid_mma_kernel,
                             cudaFuncAttributeMaxDynamicSharedMemorySize, SMEM_MID_BYTES);
    }

    cvt_kernel<<<2048, 256>>>(x, p_xh, B_ * T_ * D_ / 2);
    cvt_kernel<<<512, 256>>>(W_enc, p_We, N_ * D_ * H_ / 2);
    cvt_kernel<<<512, 256>>>(W_dec, p_Wd, N_ * H_ * D_ / 2);
    cvt_kernel<<<256, 256>>>(W_base, p_Wb, D_ * D_ / 2);
    cvt_kernel<<<128, 256>>>(W_down, p_Wn, N_ * D_ * R_ / 2);
    cvt_kernel<<<128, 256>>>(W_up, p_Wu, N_ * R_ * D_ / 2);
    zero_losses_kernel<<<1, 128>>>();

    dim3 g1(T_ / 128, B_, N_);
    disc_mma_kernel<<<g1, 256, SMEM_DISC_BYTES>>>(x, b_enc, b_dec);

    argmin_kernel<<<1, 32>>>(cidx);

    dim3 g2(T_ / 128, B_);
    mid_mma_kernel<<<g2, 256, SMEM_MID_BYTES>>>(b_down);

    dim3 g3(T_ / 128, D_ / 128, B_);
    out_mma_kernel<<<g3, 256, SMEM_OUT_BYTES>>>(b_base, b_up, out);
}

// round 15
// speedup vs baseline: 6.3333x; 1.0127x over previous
#include <cuda_runtime.h>
#include <cuda_fp16.h>
#include <cstdint>

#define B_ 16
#define T_ 1024
#define D_ 1024
#define H_ 256
#define R_ 64
#define N_ 8

// u32 strides
#define ASTRU 20    // A stage row: 32 halves + pad = 80 B
#define BSTRU 68    // B stage: 32 rows x (128 halves + pad) = 272 B/row
#define MSTRU 36    // mid B stage: 32 rows x (64 halves + pad) = 144 B/row
#define HSTRU 132   // H: 128 rows x (256 halves + pad) = 528 B/row

#define SA_SZ (128 * ASTRU)     // 2560 u32
#define SA64_SZ (64 * ASTRU)    // 1280 u32
#define SB_SZ (32 * BSTRU)      // 2176 u32
#define SM_SZ (32 * MSTRU)      // 1152 u32
#define OFF_B (4 * SA_SZ)       // 10240
#define OFF_H (OFF_B + 4 * SB_SZ)                   // 18944
#define SMEM_OUT_BYTES  (OFF_H * 4)                 // 75776
#define SMEM_DISC_BYTES ((OFF_H + 128 * HSTRU) * 4) // 143360
#define SMEM_MID_BYTES  ((4 * SA64_SZ + 4 * SM_SZ) * 4) // 38912

#define DISC_BLOCKS (8 * 16 * 8)   // 1024

// ---------------- scratch ----------------
__device__ float g_losses[N_ * B_];
__device__ int   g_adp[B_];
__device__ int   g_done;
__device__ __align__(256) __half g_xh [(size_t)B_ * T_ * D_];
__device__ __align__(256) __half g_Weh[(size_t)N_ * D_ * H_];
__device__ __align__(256) __half g_Wdh[(size_t)N_ * H_ * D_];
__device__ __align__(256) __half g_Wbh[(size_t)D_ * D_];
__device__ __align__(256) __half g_Wnh[(size_t)N_ * D_ * R_];
__device__ __align__(256) __half g_Wuh[(size_t)N_ * R_ * D_];
__device__ __align__(256) __half g_midh[(size_t)B_ * T_ * R_];

// ---------------- low-level helpers ----------------
__device__ __forceinline__ uint32_t smem_u32(const void* p) {
    uint32_t a;
    asm("{ .reg .u64 t; cvta.to.shared.u64 t, %1; cvt.u32.u64 %0, t; }" : "=r"(a) : "l"(p));
    return a;
}
#define CP_ASYNC16(s, g) \
    asm volatile("cp.async.cg.shared.global [%0], [%1], 16;" :: "r"(s), "l"((const void*)(g)))
#define CP_COMMIT() asm volatile("cp.async.commit_group;" ::: "memory")
#define CP_WAIT(n)  asm volatile("cp.async.wait_group %0;" :: "n"(n) : "memory")

__device__ __forceinline__ void ldsm4(uint32_t* r, uint32_t addr) {
    asm volatile("ldmatrix.sync.aligned.m8n8.x4.shared.b16 {%0,%1,%2,%3}, [%4];"
                 : "=r"(r[0]), "=r"(r[1]), "=r"(r[2]), "=r"(r[3]) : "r"(addr));
}
__device__ __forceinline__ void ldsm4t(uint32_t* r, uint32_t addr) {
    asm volatile("ldmatrix.sync.aligned.m8n8.x4.trans.shared.b16 {%0,%1,%2,%3}, [%4];"
                 : "=r"(r[0]), "=r"(r[1]), "=r"(r[2]), "=r"(r[3]) : "r"(addr));
}
__device__ __forceinline__ void mma16(float c[4], const uint32_t a[4], const uint32_t b[2]) {
    asm volatile("mma.sync.aligned.m16n8k16.row.col.f32.f16.f16.f32 "
                 "{%0,%1,%2,%3}, {%4,%5,%6,%7}, {%8,%9}, {%0,%1,%2,%3};"
                 : "+f"(c[0]), "+f"(c[1]), "+f"(c[2]), "+f"(c[3])
                 : "r"(a[0]), "r"(a[1]), "r"(a[2]), "r"(a[3]), "r"(b[0]), "r"(b[1]));
}
__device__ __forceinline__ uint32_t packh2(float lo, float hi) {
    __half2 h = __floats2half2_rn(lo, hi);
    return *reinterpret_cast<uint32_t*>(&h);
}

// cp.async slab loaders. A128: 128 rows x 32 halves (256 thr).
__device__ __forceinline__ void issueA(uint32_t sA, const __half* g, int ld, int tid) {
#pragma unroll
    for (int l = 0; l < 2; l++) {
        int s = tid + l * 256, row = s >> 2, j = s & 3;
        CP_ASYNC16(sA + (uint32_t)(row * ASTRU + j * 4) * 4, g + (size_t)row * ld + j * 8);
    }
}
// A64: 64 rows x 32 halves (exactly 256 ops)
__device__ __forceinline__ void issueA64(uint32_t sA, const __half* g, int ld, int tid) {
    int row = tid >> 2, j = tid & 3;
    CP_ASYNC16(sA + (uint32_t)(row * ASTRU + j * 4) * 4, g + (size_t)row * ld + j * 8);
}
// B: 32 rows x 128 halves
__device__ __forceinline__ void issueB(uint32_t sB, const __half* g, int ld, int tid) {
#pragma unroll
    for (int l = 0; l < 2; l++) {
        int s = tid + l * 256, row = s >> 4, j = s & 15;
        CP_ASYNC16(sB + (uint32_t)(row * BSTRU + j * 4) * 4, g + (size_t)row * ld + j * 8);
    }
}
// mid B: 32 rows x 64 halves
__device__ __forceinline__ void issueBm(uint32_t sB, const __half* g, int tid) {
    int row = tid >> 3, j = tid & 7;
    CP_ASYNC16(sB + (uint32_t)(row * MSTRU + j * 4) * 4, g + (size_t)row * R_ + j * 8);
}

// Proven fragment path: A via ldsm4, B via ldsm4t.
template<int MT, int NP>
__device__ __forceinline__ void frag_compute(uint32_t aBase, uint32_t bBase, int bstr,
                                             float (*c)[2 * NP][4], int lane) {
    const int l16 = lane & 15, hi = lane >> 4;
#pragma unroll
    for (int ks = 0; ks < 2; ks++) {
        uint32_t a[MT][4], b4n[NP][4];
#pragma unroll
        for (int mt = 0; mt < MT; mt++)
            ldsm4(a[mt], aBase + (uint32_t)((mt * 16 + l16) * 80 + ks * 32 + hi * 16));
#pragma unroll
        for (int np = 0; np < NP; np++)
            ldsm4t(b4n[np], bBase + (uint32_t)((ks * 16 + l16) * bstr + np * 32 + hi * 16));
#pragma unroll
        for (int mt = 0; mt < MT; mt++)
#pragma unroll
            for (int np = 0; np < NP; np++) {
                mma16(c[mt][np * 2 + 0], a[mt], b4n[np] + 0);
                mma16(c[mt][np * 2 + 1], a[mt], b4n[np] + 2);
            }
    }
}

// Disc phase 2: A from H via proven SCALAR u32 reads; B via proven ldsm4t.
__device__ __forceinline__ void frag_compute_h(const uint32_t* __restrict__ Hw, uint32_t bBase,
                                               float (*c)[4][4], int lane, int hcoff) {
    const int lr = lane >> 2, lk = lane & 3;
    const int l16 = lane & 15, hi = lane >> 4;
#pragma unroll
    for (int ks = 0; ks < 2; ks++) {
        uint32_t a[4][4], b4n[2][4];
#pragma unroll
        for (int mt = 0; mt < 4; mt++) {
            const uint32_t* ap = Hw + (mt * 16 + lr) * HSTRU + hcoff + ks * 8 + lk;
            a[mt][0] = ap[0];
            a[mt][1] = ap[8 * HSTRU];
            a[mt][2] = ap[4];
            a[mt][3] = ap[8 * HSTRU + 4];
        }
#pragma unroll
        for (int np = 0; np < 2; np++)
            ldsm4t(b4n[np], bBase + (uint32_t)((ks * 16 + l16) * 272 + np * 32 + hi * 16));
#pragma unroll
        for (int mt = 0; mt < 4; mt++)
#pragma unroll
            for (int np = 0; np < 2; np++) {
                mma16(c[mt][np * 2 + 0], a[mt], b4n[np] + 0);
                mma16(c[mt][np * 2 + 1], a[mt], b4n[np] + 2);
            }
    }
}

// ---------------- prep: fused fp32->fp16 cvt of all tensors + zero ----------------
// float4-unit segment offsets (compile-time)
#define S_X  4194304u
#define S_WE (S_X + 524288u)
#define S_WD (S_WE + 524288u)
#define S_WB (S_WD + 262144u)
#define S_WN (S_WB + 131072u)
#define S_WU (S_WN + 131072u)   // total 5767168

__global__ void prep_kernel(const float* __restrict__ x, const float* __restrict__ We,
                            const float* __restrict__ Wd, const float* __restrict__ Wb,
                            const float* __restrict__ Wn, const float* __restrict__ Wu) {
    uint32_t idx = blockIdx.x * blockDim.x + threadIdx.x;
    const uint32_t stride = gridDim.x * blockDim.x;
    if (blockIdx.x == 0) {
        if (threadIdx.x < N_ * B_) g_losses[threadIdx.x] = 0.f;
        if (threadIdx.x == N_ * B_) g_done = 0;
    }
    for (; idx < S_WU; idx += stride) {
        const float* src; __half* dst; uint32_t off;
        if (idx < S_X)       { src = x;  dst = g_xh;  off = idx; }
        else if (idx < S_WE) { src = We; dst = g_Weh; off = idx - S_X; }
        else if (idx < S_WD) { src = Wd; dst = g_Wdh; off = idx - S_WE; }
        else if (idx < S_WB) { src = Wb; dst = g_Wbh; off = idx - S_WD; }
        else if (idx < S_WN) { src = Wn; dst = g_Wnh; off = idx - S_WB; }
        else                 { src = Wu; dst = g_Wuh; off = idx - S_WN; }
        float4 v = reinterpret_cast<const float4*>(src)[off];
        uint2 u = make_uint2(packh2(v.x, v.y), packh2(v.z, v.w));
        reinterpret_cast<uint2*>(dst)[off] = u;
    }
}

// ---------------- disc loss (argmin folded in) ----------------
__global__ __launch_bounds__(256)
void disc_mma_kernel(const float* __restrict__ xf,
                     const float* __restrict__ b_enc, const float* __restrict__ b_dec,
                     const int* __restrict__ cidx) {
    extern __shared__ uint32_t sm[];
    const uint32_t sb = smem_u32(sm);
    const int tid = threadIdx.x, wid = tid >> 5, lane = tid & 31;
    const int RM = (wid & 1) * 64, CN = (wid >> 1) * 32;
    const int lr = lane >> 2, lk = lane & 3;
    const int n = blockIdx.z, b = blockIdx.y, t0 = blockIdx.x * 128;

    const __half* xb = g_xh + ((size_t)b * T_ + t0) * D_;
    const float* xbf = xf + ((size_t)b * T_ + t0) * D_;
    const __half* We = g_Weh + (size_t)n * D_ * H_;
    const __half* Wd = g_Wdh + (size_t)n * H_ * D_;

    float c[4][4][4];
#pragma unroll
    for (int mt = 0; mt < 4; mt++)
#pragma unroll
        for (int nt = 0; nt < 4; nt++)
#pragma unroll
            for (int i = 0; i < 4; i++) c[mt][nt][i] = 0.f;

    // ===== Phase 1: 64 chunks (nc = q>>5, kc = q&31) =====
    for (int q = 0; q < 2; q++) {
        issueA(sb + (uint32_t)(q & 3) * SA_SZ * 4, xb + (q & 31) * 32, D_, tid);
        issueB(sb + (uint32_t)(OFF_B + (q & 3) * SB_SZ) * 4,
               We + (size_t)(q & 31) * 32 * H_ + (q >> 5) * 128, H_, tid);
        CP_COMMIT();
    }
    for (int q = 0; q < 64; q++) {
        if (q + 2 < 64) {
            int p = q + 2;
            issueA(sb + (uint32_t)(p & 3) * SA_SZ * 4, xb + (p & 31) * 32, D_, tid);
            issueB(sb + (uint32_t)(OFF_B + (p & 3) * SB_SZ) * 4,
                   We + (size_t)(p & 31) * 32 * H_ + (p >> 5) * 128, H_, tid);
            CP_COMMIT();
        }
        if (q + 2 < 64) { CP_WAIT(2); } else if (q + 1 < 64) { CP_WAIT(1); } else { CP_WAIT(0); }
        __syncthreads();
        frag_compute<4, 2>(sb + (uint32_t)(q & 3) * SA_SZ * 4 + RM * 80,
                           sb + (uint32_t)(OFF_B + (q & 3) * SB_SZ) * 4 + CN * 2, 272, c, lane);
        if ((q & 31) == 31) {
            int nc = q >> 5;
#pragma unroll
            for (int mt = 0; mt < 4; mt++) {
                int r = RM + mt * 16 + lr;
#pragma unroll
                for (int nt = 0; nt < 4; nt++) {
                    int col = nc * 128 + CN + nt * 8 + lk * 2;
                    float be0 = __ldg(b_enc + n * H_ + col);
                    float be1 = __ldg(b_enc + n * H_ + col + 1);
                    float v0 = c[mt][nt][0] + be0, v1 = c[mt][nt][1] + be1;
                    float v2 = c[mt][nt][2] + be0, v3 = c[mt][nt][3] + be1;
                    sm[OFF_H + r * HSTRU + (col >> 1)] =
                        packh2(v0 > 0.f ? v0 : 0.f, v1 > 0.f ? v1 : 0.f);
                    sm[OFF_H + (r + 8) * HSTRU + (col >> 1)] =
                        packh2(v2 > 0.f ? v2 : 0.f, v3 > 0.f ? v3 : 0.f);
                    c[mt][nt][0] = c[mt][nt][1] = c[mt][nt][2] = c[mt][nt][3] = 0.f;
                }
            }
        }
    }

    // ===== Phase 2: 64 chunks (dc = q>>3, hc = q&7), A = H (scalar reads) =====
    float ss = 0.f;
    for (int q = 0; q < 2; q++) {
        issueB(sb + (uint32_t)(OFF_B + (q & 3) * SB_SZ) * 4,
               Wd + (size_t)(q & 7) * 32 * D_ + (q >> 3) * 128, D_, tid);
        CP_COMMIT();
    }
    for (int q = 0; q < 64; q++) {
        if (q + 2 < 64) {
            int p = q + 2;
            issueB(sb + (uint32_t)(OFF_B + (p & 3) * SB_SZ) * 4,
                   Wd + (size_t)(p & 7) * 32 * D_ + (p >> 3) * 128, D_, tid);
            CP_COMMIT();
        }
        if (q + 2 < 64) { CP_WAIT(2); } else if (q + 1 < 64) { CP_WAIT(1); } else { CP_WAIT(0); }
        __syncthreads();
        frag_compute_h(sm + OFF_H + RM * HSTRU,
                       sb + (uint32_t)(OFF_B + (q & 3) * SB_SZ) * 4 + CN * 2,
                       c, lane, (q & 7) * 16);
        if ((q & 7) == 7) {
            int dc = q >> 3;
#pragma unroll
            for (int mt = 0; mt < 4; mt++) {
                int r = RM + mt * 16 + lr;
#pragma unroll
                for (int nt = 0; nt < 4; nt++) {
                    int col = dc * 128 + CN + nt * 8 + lk * 2;
                    float bd0 = __ldg(b_dec + n * D_ + col);
                    float bd1 = __ldg(b_dec + n * D_ + col + 1);
                    float2 x0 = *reinterpret_cast<const float2*>(xbf + (size_t)r * D_ + col);
                    float2 x1 = *reinterpret_cast<const float2*>(xbf + (size_t)(r + 8) * D_ + col);
                    float e0 = c[mt][nt][0] + bd0 - x0.x;
                    float e1 = c[mt][nt][1] + bd1 - x0.y;
                    float e2 = c[mt][nt][2] + bd0 - x1.x;
                    float e3 = c[mt][nt][3] + bd1 - x1.y;
                    ss = fmaf(e0, e0, ss); ss = fmaf(e1, e1, ss);
                    ss = fmaf(e2, e2, ss); ss = fmaf(e3, e3, ss);
                    c[mt][nt][0] = c[mt][nt][1] = c[mt][nt][2] = c[mt][nt][3] = 0.f;
                }
            }
        }
    }

#pragma unroll
    for (int o = 16; o > 0; o >>= 1)
        ss += __shfl_down_sync(0xffffffffu, ss, o);
    __shared__ float red[8];
    __shared__ int lastFlag;
    if (lane == 0) red[wid] = ss;
    __syncthreads();
    if (tid == 0) {
        float s = 0.f;
#pragma unroll
        for (int i = 0; i < 8; i++) s += red[i];
        atomicAdd(&g_losses[n * B_ + b], s);
        __threadfence();
        int t = atomicAdd(&g_done, 1);
        lastFlag = (t == DISC_BLOCKS - 1) ? 1 : 0;
    }
    __syncthreads();
    // last block computes routing (16 threads in parallel)
    if (lastFlag && tid < B_) {
        volatile float* gl = g_losses;
        float best = gl[tid];
        int bi = 0;
        for (int nn = 1; nn < N_; nn++) {
            float v = gl[nn * B_ + tid];
            if (v < best) { best = v; bi = nn; }
        }
        g_adp[tid] = __ldg(cidx + bi);
    }
}

// ---------------- mid = relu(x @ W_down[adp] + b_down) -> g_midh (fp16 MMA, M=64) ----------------
__global__ __launch_bounds__(256)
void mid_mma_kernel(const float* __restrict__ b_down) {
    extern __shared__ uint32_t sm[];
    const uint32_t sb = smem_u32(sm);
    const int tid = threadIdx.x, wid = tid >> 5, lane = tid & 31;
    const int RM = (wid & 3) * 16, CN = (wid >> 2) * 32;  // warps 4(M) x 2(N)
    const int lr = lane >> 2, lk = lane & 3;
    const int b = blockIdx.y, t0 = blockIdx.x * 64;
    const int a = g_adp[b];

    const __half* xb = g_xh + ((size_t)b * T_ + t0) * D_;
    const __half* Wn = g_Wnh + (size_t)a * D_ * R_;

    float c[1][4][4];
#pragma unroll
    for (int nt = 0; nt < 4; nt++)
#pragma unroll
        for (int i = 0; i < 4; i++) c[0][nt][i] = 0.f;

    for (int q = 0; q < 2; q++) {
        issueA64(sb + (uint32_t)(q & 3) * SA64_SZ * 4, xb + q * 32, D_, tid);
        issueBm(sb + (uint32_t)(4 * SA64_SZ + (q & 3) * SM_SZ) * 4, Wn + (size_t)q * 32 * R_, tid);
        CP_COMMIT();
    }
    for (int q = 0; q < 32; q++) {
        if (q + 2 < 32) {
            int p = q + 2;
            issueA64(sb + (uint32_t)(p & 3) * SA64_SZ * 4, xb + p * 32, D_, tid);
            issueBm(sb + (uint32_t)(4 * SA64_SZ + (p & 3) * SM_SZ) * 4, Wn + (size_t)p * 32 * R_, tid);
            CP_COMMIT();
        }
        if (q + 2 < 32) { CP_WAIT(2); } else if (q + 1 < 32) { CP_WAIT(1); } else { CP_WAIT(0); }
        __syncthreads();
        frag_compute<1, 2>(sb + (uint32_t)(q & 3) * SA64_SZ * 4 + RM * 80,
                           sb + (uint32_t)(4 * SA64_SZ + (q & 3) * SM_SZ) * 4 + CN * 2, 144, c, lane);
    }

    {
        int r = RM + lr;
#pragma unroll
        for (int nt = 0; nt < 4; nt++) {
            int col = CN + nt * 8 + lk * 2;
            float bd0 = __ldg(b_down + a * R_ + col);
            float bd1 = __ldg(b_down + a * R_ + col + 1);
            float v0 = c[0][nt][0] + bd0, v1 = c[0][nt][1] + bd1;
            float v2 = c[0][nt][2] + bd0, v3 = c[0][nt][3] + bd1;
            *reinterpret_cast<uint32_t*>(g_midh + ((size_t)b * T_ + t0 + r) * R_ + col) =
                packh2(v0 > 0.f ? v0 : 0.f, v1 > 0.f ? v1 : 0.f);
            *reinterpret_cast<uint32_t*>(g_midh + ((size_t)b * T_ + t0 + r + 8) * R_ + col) =
                packh2(v2 > 0.f ? v2 : 0.f, v3 > 0.f ? v3 : 0.f);
        }
    }
}

// ---------------- out = x@W_base + mid@W_up + biases ----------------
__global__ __launch_bounds__(256)
void out_mma_kernel(const float* __restrict__ b_base, const float* __restrict__ b_up,
                    float* __restrict__ out) {
    extern __shared__ uint32_t sm[];
    const uint32_t sb = smem_u32(sm);
    const int tid = threadIdx.x, wid = tid >> 5, lane = tid & 31;
    const int RM = (wid & 1) * 64, CN = (wid >> 1) * 32;
    const int lr = lane >> 2, lk = lane & 3;
    const int b = blockIdx.z, e0 = blockIdx.y * 128, t0 = blockIdx.x * 128;
    const int a = g_adp[b];

    const __half* xb = g_xh + ((size_t)b * T_ + t0) * D_;
    const __half* mb = g_midh + ((size_t)b * T_ + t0) * R_;
    const __half* Wb = g_Wbh;
    const __half* Wu = g_Wuh + (size_t)a * R_ * D_;

    float c[4][4][4];
#pragma unroll
    for (int mt = 0; mt < 4; mt++)
#pragma unroll
        for (int nt = 0; nt < 4; nt++)
#pragma unroll
            for (int i = 0; i < 4; i++) c[mt][nt][i] = 0.f;

    const int NC = 34;
    for (int q = 0; q < 2; q++) {
        issueA(sb + (uint32_t)(q & 3) * SA_SZ * 4, xb + q * 32, D_, tid);
        issueB(sb + (uint32_t)(OFF_B + (q & 3) * SB_SZ) * 4, Wb + (size_t)q * 32 * D_ + e0, D_, tid);
        CP_COMMIT();
    }
    for (int q = 0; q < NC; q++) {
        if (q + 2 < NC) {
            int p = q + 2;
            if (p < 32) {
                issueA(sb + (uint32_t)(p & 3) * SA_SZ * 4, xb + p * 32, D_, tid);
                issueB(sb + (uint32_t)(OFF_B + (p & 3) * SB_SZ) * 4,
                       Wb + (size_t)p * 32 * D_ + e0, D_, tid);
            } else {
                issueA(sb + (uint32_t)(p & 3) * SA_SZ * 4, mb + (p - 32) * 32, R_, tid);
                issueB(sb + (uint32_t)(OFF_B + (p & 3) * SB_SZ) * 4,
                       Wu + (size_t)(p - 32) * 32 * D_ + e0, D_, tid);
            }
            CP_COMMIT();
        }
        if (q + 2 < NC) { CP_WAIT(2); } else if (q + 1 < NC) { CP_WAIT(1); } else { CP_WAIT(0); }
        __syncthreads();
        frag_compute<4, 2>(sb + (uint32_t)(q & 3) * SA_SZ * 4 + RM * 80,
                           sb + (uint32_t)(OFF_B + (q & 3) * SB_SZ) * 4 + CN * 2, 272, c, lane);
    }

#pragma unroll
    for (int mt = 0; mt < 4; mt++) {
        int r = RM + mt * 16 + lr;
#pragma unroll
        for (int nt = 0; nt < 4; nt++) {
            int col = e0 + CN + nt * 8 + lk * 2;
            float bb0 = __ldg(b_base + col) + __ldg(b_up + a * D_ + col);
            float bb1 = __ldg(b_base + col + 1) + __ldg(b_up + a * D_ + col + 1);
            float2 v0 = make_float2(c[mt][nt][0] + bb0, c[mt][nt][1] + bb1);
            float2 v1 = make_float2(c[mt][nt][2] + bb0, c[mt][nt][3] + bb1);
            *reinterpret_cast<float2*>(out + ((size_t)b * T_ + t0 + r) * D_ + col) = v0;
            *reinterpret_cast<float2*>(out + ((size_t)b * T_ + t0 + r + 8) * D_ + col) = v1;
        }
    }
}

// ---------------------------------------------------------------------------
extern "C" void kernel_launch(void* const* d_in, const int* in_sizes, int n_in,
                              void* d_out, int out_size) {
    const float* x      = (const float*)d_in[0];
    const float* W_base = (const float*)d_in[1];
    const float* b_base = (const float*)d_in[2];
    const float* W_enc  = (const float*)d_in[3];
    const float* b_enc  = (const float*)d_in[4];
    const float* W_dec  = (const float*)d_in[5];
    const float* b_dec  = (const float*)d_in[6];
    const float* W_down = (const float*)d_in[7];
    const float* b_down = (const float*)d_in[8];
    const float* W_up   = (const float*)d_in[9];
    const float* b_up   = (const float*)d_in[10];
    const int*   cidx   = (const int*)d_in[11];
    float* out = (float*)d_out;

    static bool init = false;
    if (!init) {
        init = true;
        cudaFuncSetAttribute(disc_mma_kernel,
                             cudaFuncAttributeMaxDynamicSharedMemorySize, SMEM_DISC_BYTES);
        cudaFuncSetAttribute(out_mma_kernel,
                             cudaFuncAttributeMaxDynamicSharedMemorySize, SMEM_OUT_BYTES);
        cudaFuncSetAttribute(mid_mma_kernel,
                             cudaFuncAttributeMaxDynamicSharedMemorySize, SMEM_MID_BYTES);
    }

    prep_kernel<<<2048, 256>>>(x, W_enc, W_dec, W_base, W_down, W_up);

    dim3 g1(T_ / 128, B_, N_);
    disc_mma_kernel<<<g1, 256, SMEM_DISC_BYTES>>>(x, b_enc, b_dec, cidx);

    dim3 g2(T_ / 64, B_);
    mid_mma_kernel<<<g2, 256, SMEM_MID_BYTES>>>(b_down);

    dim3 g3(T_ / 128, D_ / 128, B_);
    out_mma_kernel<<<g3, 256, SMEM_OUT_BYTES>>>(b_base, b_up, out);
}

// round 17
// speedup vs baseline: 6.4988x; 1.0261x over previous
#include <cuda_runtime.h>
#include <cuda_fp16.h>
#include <cstdint>

#define B_ 16
#define T_ 1024
#define D_ 1024
#define H_ 256
#define R_ 64
#define N_ 8

// u32 strides
#define ASTRU 20    // A stage row: 32 halves + pad = 80 B
#define BSTRU 68    // B stage: 32 rows x (128 halves + pad) = 272 B/row
#define MSTRU 36    // mid B stage: 32 rows x (64 halves + pad) = 144 B/row
#define HSTRU 132   // H: 128 rows x (256 halves + pad) = 528 B/row

#define SA_SZ (128 * ASTRU)     // 2560 u32
#define SA64_SZ (64 * ASTRU)    // 1280 u32
#define SB_SZ (32 * BSTRU)      // 2176 u32
#define SM_SZ (32 * MSTRU)      // 1152 u32

// out kernel: 4 stages
#define OOFF_B (4 * SA_SZ)                          // 10240
#define SMEM_OUT_BYTES  ((OOFF_B + 4 * SB_SZ) * 4)  // 75776
// disc kernel: 8 stages
#define DOFF_B (8 * SA_SZ)                          // 20480
#define DOFF_H (DOFF_B + 8 * SB_SZ)                 // 37888
#define SMEM_DISC_BYTES ((DOFF_H + 128 * HSTRU) * 4) // 219136
#define SMEM_MID_BYTES  ((4 * SA64_SZ + 4 * SM_SZ) * 4) // 38912

#define DISC_BLOCKS (8 * 16 * 8)   // 1024

// ---------------- scratch ----------------
__device__ float g_losses[N_ * B_];
__device__ int   g_adp[B_];
__device__ int   g_done;
__device__ __align__(256) __half g_xh [(size_t)B_ * T_ * D_];
__device__ __align__(256) __half g_Weh[(size_t)N_ * D_ * H_];
__device__ __align__(256) __half g_Wdh[(size_t)N_ * H_ * D_];
__device__ __align__(256) __half g_Wbh[(size_t)D_ * D_];
__device__ __align__(256) __half g_Wnh[(size_t)N_ * D_ * R_];
__device__ __align__(256) __half g_Wuh[(size_t)N_ * R_ * D_];
__device__ __align__(256) __half g_midh[(size_t)B_ * T_ * R_];

// ---------------- low-level helpers ----------------
__device__ __forceinline__ uint32_t smem_u32(const void* p) {
    uint32_t a;
    asm("{ .reg .u64 t; cvta.to.shared.u64 t, %1; cvt.u32.u64 %0, t; }" : "=r"(a) : "l"(p));
    return a;
}
#define CP_ASYNC16(s, g) \
    asm volatile("cp.async.cg.shared.global [%0], [%1], 16;" :: "r"(s), "l"((const void*)(g)))
#define CP_COMMIT() asm volatile("cp.async.commit_group;" ::: "memory")
#define CP_WAIT(n)  asm volatile("cp.async.wait_group %0;" :: "n"(n) : "memory")

__device__ __forceinline__ void ldsm4(uint32_t* r, uint32_t addr) {
    asm volatile("ldmatrix.sync.aligned.m8n8.x4.shared.b16 {%0,%1,%2,%3}, [%4];"
                 : "=r"(r[0]), "=r"(r[1]), "=r"(r[2]), "=r"(r[3]) : "r"(addr));
}
__device__ __forceinline__ void ldsm4t(uint32_t* r, uint32_t addr) {
    asm volatile("ldmatrix.sync.aligned.m8n8.x4.trans.shared.b16 {%0,%1,%2,%3}, [%4];"
                 : "=r"(r[0]), "=r"(r[1]), "=r"(r[2]), "=r"(r[3]) : "r"(addr));
}
__device__ __forceinline__ void mma16(float c[4], const uint32_t a[4], const uint32_t b[2]) {
    asm volatile("mma.sync.aligned.m16n8k16.row.col.f32.f16.f16.f32 "
                 "{%0,%1,%2,%3}, {%4,%5,%6,%7}, {%8,%9}, {%0,%1,%2,%3};"
                 : "+f"(c[0]), "+f"(c[1]), "+f"(c[2]), "+f"(c[3])
                 : "r"(a[0]), "r"(a[1]), "r"(a[2]), "r"(a[3]), "r"(b[0]), "r"(b[1]));
}
__device__ __forceinline__ uint32_t packh2(float lo, float hi) {
    __half2 h = __floats2half2_rn(lo, hi);
    return *reinterpret_cast<uint32_t*>(&h);
}

// cp.async slab loaders. A128: 128 rows x 32 halves (256 thr).
__device__ __forceinline__ void issueA(uint32_t sA, const __half* g, int ld, int tid) {
#pragma unroll
    for (int l = 0; l < 2; l++) {
        int s = tid + l * 256, row = s >> 2, j = s & 3;
        CP_ASYNC16(sA + (uint32_t)(row * ASTRU + j * 4) * 4, g + (size_t)row * ld + j * 8);
    }
}
// A64: 64 rows x 32 halves
__device__ __forceinline__ void issueA64(uint32_t sA, const __half* g, int ld, int tid) {
    int row = tid >> 2, j = tid & 3;
    CP_ASYNC16(sA + (uint32_t)(row * ASTRU + j * 4) * 4, g + (size_t)row * ld + j * 8);
}
// B: 32 rows x 128 halves
__device__ __forceinline__ void issueB(uint32_t sB, const __half* g, int ld, int tid) {
#pragma unroll
    for (int l = 0; l < 2; l++) {
        int s = tid + l * 256, row = s >> 4, j = s & 15;
        CP_ASYNC16(sB + (uint32_t)(row * BSTRU + j * 4) * 4, g + (size_t)row * ld + j * 8);
    }
}
// mid B: 32 rows x 64 halves
__device__ __forceinline__ void issueBm(uint32_t sB, const __half* g, int tid) {
    int row = tid >> 3, j = tid & 7;
    CP_ASYNC16(sB + (uint32_t)(row * MSTRU + j * 4) * 4, g + (size_t)row * R_ + j * 8);
}

// Proven fragment path: A via ldsm4, B via ldsm4t.
template<int MT, int NP>
__device__ __forceinline__ void frag_compute(uint32_t aBase, uint32_t bBase, int bstr,
                                             float (*c)[2 * NP][4], int lane) {
    const int l16 = lane & 15, hi = lane >> 4;
#pragma unroll
    for (int ks = 0; ks < 2; ks++) {
        uint32_t a[MT][4], b4n[NP][4];
#pragma unroll
        for (int mt = 0; mt < MT; mt++)
            ldsm4(a[mt], aBase + (uint32_t)((mt * 16 + l16) * 80 + ks * 32 + hi * 16));
#pragma unroll
        for (int np = 0; np < NP; np++)
            ldsm4t(b4n[np], bBase + (uint32_t)((ks * 16 + l16) * bstr + np * 32 + hi * 16));
#pragma unroll
        for (int mt = 0; mt < MT; mt++)
#pragma unroll
            for (int np = 0; np < NP; np++) {
                mma16(c[mt][np * 2 + 0], a[mt], b4n[np] + 0);
                mma16(c[mt][np * 2 + 1], a[mt], b4n[np] + 2);
            }
    }
}

// Disc phase 2: A from H via proven SCALAR u32 reads; B via proven ldsm4t.
__device__ __forceinline__ void frag_compute_h(const uint32_t* __restrict__ Hw, uint32_t bBase,
                                               float (*c)[4][4], int lane, int hcoff) {
    const int lr = lane >> 2, lk = lane & 3;
    const int l16 = lane & 15, hi = lane >> 4;
#pragma unroll
    for (int ks = 0; ks < 2; ks++) {
        uint32_t a[4][4], b4n[2][4];
#pragma unroll
        for (int mt = 0; mt < 4; mt++) {
            const uint32_t* ap = Hw + (mt * 16 + lr) * HSTRU + hcoff + ks * 8 + lk;
            a[mt][0] = ap[0];
            a[mt][1] = ap[8 * HSTRU];
            a[mt][2] = ap[4];
            a[mt][3] = ap[8 * HSTRU + 4];
        }
#pragma unroll
        for (int np = 0; np < 2; np++)
            ldsm4t(b4n[np], bBase + (uint32_t)((ks * 16 + l16) * 272 + np * 32 + hi * 16));
#pragma unroll
        for (int mt = 0; mt < 4; mt++)
#pragma unroll
            for (int np = 0; np < 2; np++) {
                mma16(c[mt][np * 2 + 0], a[mt], b4n[np] + 0);
                mma16(c[mt][np * 2 + 1], a[mt], b4n[np] + 2);
            }
    }
}

// ---------------- prep: fused fp32->fp16 cvt + zero ----------------
#define S_X  4194304u
#define S_WE (S_X + 524288u)
#define S_WD (S_WE + 524288u)
#define S_WB (S_WD + 262144u)
#define S_WN (S_WB + 131072u)
#define S_WU (S_WN + 131072u)

__global__ void prep_kernel(const float* __restrict__ x, const float* __restrict__ We,
                            const float* __restrict__ Wd, const float* __restrict__ Wb,
                            const float* __restrict__ Wn, const float* __restrict__ Wu) {
    uint32_t idx = blockIdx.x * blockDim.x + threadIdx.x;
    const uint32_t stride = gridDim.x * blockDim.x;
    if (blockIdx.x == 0) {
        if (threadIdx.x < N_ * B_) g_losses[threadIdx.x] = 0.f;
        if (threadIdx.x == N_ * B_) g_done = 0;
    }
    for (; idx < S_WU; idx += stride) {
        const float* src; __half* dst; uint32_t off;
        if (idx < S_X)       { src = x;  dst = g_xh;  off = idx; }
        else if (idx < S_WE) { src = We; dst = g_Weh; off = idx - S_X; }
        else if (idx < S_WD) { src = Wd; dst = g_Wdh; off = idx - S_WE; }
        else if (idx < S_WB) { src = Wb; dst = g_Wbh; off = idx - S_WD; }
        else if (idx < S_WN) { src = Wn; dst = g_Wnh; off = idx - S_WB; }
        else                 { src = Wu; dst = g_Wuh; off = idx - S_WN; }
        float4 v = reinterpret_cast<const float4*>(src)[off];
        uint2 u = make_uint2(packh2(v.x, v.y), packh2(v.z, v.w));
        reinterpret_cast<uint2*>(dst)[off] = u;
    }
}

// ---------------- disc loss (8-stage paired pipeline, argmin folded in) ----------------
__global__ __launch_bounds__(256)
void disc_mma_kernel(const float* __restrict__ xf,
                     const float* __restrict__ b_enc, const float* __restrict__ b_dec,
                     const int* __restrict__ cidx) {
    extern __shared__ uint32_t sm[];
    const uint32_t sb = smem_u32(sm);
    const int tid = threadIdx.x, wid = tid >> 5, lane = tid & 31;
    const int RM = (wid & 1) * 64, CN = (wid >> 1) * 32;
    const int lr = lane >> 2, lk = lane & 3;
    const int n = blockIdx.z, b = blockIdx.y, t0 = blockIdx.x * 128;

    const __half* xb = g_xh + ((size_t)b * T_ + t0) * D_;
    const float* xbf = xf + ((size_t)b * T_ + t0) * D_;
    const __half* We = g_Weh + (size_t)n * D_ * H_;
    const __half* Wd = g_Wdh + (size_t)n * H_ * D_;

    float c[4][4][4];
#pragma unroll
    for (int mt = 0; mt < 4; mt++)
#pragma unroll
        for (int nt = 0; nt < 4; nt++)
#pragma unroll
            for (int i = 0; i < 4; i++) c[mt][nt][i] = 0.f;

    // ===== Phase 1: 64 chunks, pairs of 2 per barrier =====
    for (int q = 0; q < 4; q++) {
        issueA(sb + (uint32_t)q * SA_SZ * 4, xb + q * 32, D_, tid);
        issueB(sb + (uint32_t)(DOFF_B + q * SB_SZ) * 4, We + (size_t)q * 32 * H_, H_, tid);
        if (q & 1) CP_COMMIT();
    }
    for (int p = 0; p < 32; p++) {
        if (p + 2 < 32) {
#pragma unroll
            for (int e = 0; e < 2; e++) {
                int q = 2 * p + 4 + e;
                issueA(sb + (uint32_t)(q & 7) * SA_SZ * 4, xb + (q & 31) * 32, D_, tid);
                issueB(sb + (uint32_t)(DOFF_B + (q & 7) * SB_SZ) * 4,
                       We + (size_t)(q & 31) * 32 * H_ + (q >> 5) * 128, H_, tid);
            }
            CP_COMMIT();
        }
        if (p + 2 < 32) { CP_WAIT(2); } else if (p + 1 < 32) { CP_WAIT(1); } else { CP_WAIT(0); }
        __syncthreads();
#pragma unroll
        for (int e = 0; e < 2; e++) {
            int q = 2 * p + e;
            frag_compute<4, 2>(sb + (uint32_t)(q & 7) * SA_SZ * 4 + RM * 80,
                               sb + (uint32_t)(DOFF_B + (q & 7) * SB_SZ) * 4 + CN * 2, 272, c, lane);
            if ((q & 31) == 31) {
                int nc = q >> 5;
#pragma unroll
                for (int mt = 0; mt < 4; mt++) {
                    int r = RM + mt * 16 + lr;
#pragma unroll
                    for (int nt = 0; nt < 4; nt++) {
                        int col = nc * 128 + CN + nt * 8 + lk * 2;
                        float be0 = __ldg(b_enc + n * H_ + col);
                        float be1 = __ldg(b_enc + n * H_ + col + 1);
                        float v0 = c[mt][nt][0] + be0, v1 = c[mt][nt][1] + be1;
                        float v2 = c[mt][nt][2] + be0, v3 = c[mt][nt][3] + be1;
                        sm[DOFF_H + r * HSTRU + (col >> 1)] =
                            packh2(v0 > 0.f ? v0 : 0.f, v1 > 0.f ? v1 : 0.f);
                        sm[DOFF_H + (r + 8) * HSTRU + (col >> 1)] =
                            packh2(v2 > 0.f ? v2 : 0.f, v3 > 0.f ? v3 : 0.f);
                        c[mt][nt][0] = c[mt][nt][1] = c[mt][nt][2] = c[mt][nt][3] = 0.f;
                    }
                }
            }
        }
    }

    // ===== Phase 2: 64 chunks (dc = q>>3, hc = q&7), pairs, A = H =====
    float ss = 0.f;
    for (int q = 0; q < 4; q++) {
        issueB(sb + (uint32_t)(DOFF_B + q * SB_SZ) * 4,
               Wd + (size_t)(q & 7) * 32 * D_, D_, tid);
        if (q & 1) CP_COMMIT();
    }
    for (int p = 0; p < 32; p++) {
        if (p + 2 < 32) {
#pragma unroll
            for (int e = 0; e < 2; e++) {
                int q = 2 * p + 4 + e;
                issueB(sb + (uint32_t)(DOFF_B + (q & 7) * SB_SZ) * 4,
                       Wd + (size_t)(q & 7) * 32 * D_ + (q >> 3) * 128, D_, tid);
            }
            CP_COMMIT();
        }
        if (p + 2 < 32) { CP_WAIT(2); } else if (p + 1 < 32) { CP_WAIT(1); } else { CP_WAIT(0); }
        __syncthreads();
#pragma unroll
        for (int e = 0; e < 2; e++) {
            int q = 2 * p + e;
            frag_compute_h(sm + DOFF_H + RM * HSTRU,
                           sb + (uint32_t)(DOFF_B + (q & 7) * SB_SZ) * 4 + CN * 2,
                           c, lane, (q & 7) * 16);
            if ((q & 7) == 7) {
                int dc = q >> 3;
#pragma unroll
                for (int mt = 0; mt < 4; mt++) {
                    int r = RM + mt * 16 + lr;
#pragma unroll
                    for (int nt = 0; nt < 4; nt++) {
                        int col = dc * 128 + CN + nt * 8 + lk * 2;
                        float bd0 = __ldg(b_dec + n * D_ + col);
                        float bd1 = __ldg(b_dec + n * D_ + col + 1);
                        float2 x0 = *reinterpret_cast<const float2*>(xbf + (size_t)r * D_ + col);
                        float2 x1 = *reinterpret_cast<const float2*>(xbf + (size_t)(r + 8) * D_ + col);
                        float e0 = c[mt][nt][0] + bd0 - x0.x;
                        float e1 = c[mt][nt][1] + bd1 - x0.y;
                        float e2 = c[mt][nt][2] + bd0 - x1.x;
                        float e3 = c[mt][nt][3] + bd1 - x1.y;
                        ss = fmaf(e0, e0, ss); ss = fmaf(e1, e1, ss);
                        ss = fmaf(e2, e2, ss); ss = fmaf(e3, e3, ss);
                        c[mt][nt][0] = c[mt][nt][1] = c[mt][nt][2] = c[mt][nt][3] = 0.f;
                    }
                }
            }
        }
    }

#pragma unroll
    for (int o = 16; o > 0; o >>= 1)
        ss += __shfl_down_sync(0xffffffffu, ss, o);
    __shared__ float red[8];
    __shared__ int lastFlag;
    if (lane == 0) red[wid] = ss;
    __syncthreads();
    if (tid == 0) {
        float s = 0.f;
#pragma unroll
        for (int i = 0; i < 8; i++) s += red[i];
        atomicAdd(&g_losses[n * B_ + b], s);
        __threadfence();
        int t = atomicAdd(&g_done, 1);
        lastFlag = (t == DISC_BLOCKS - 1) ? 1 : 0;
    }
    __syncthreads();
    if (lastFlag && tid < B_) {
        volatile float* gl = g_losses;
        float best = gl[tid];
        int bi = 0;
        for (int nn = 1; nn < N_; nn++) {
            float v = gl[nn * B_ + tid];
            if (v < best) { best = v; bi = nn; }
        }
        g_adp[tid] = __ldg(cidx + bi);
    }
}

// ---------------- mid = relu(x @ W_down[adp] + b_down) -> g_midh (fp16 MMA, M=64) ----------------
__global__ __launch_bounds__(256)
void mid_mma_kernel(const float* __restrict__ b_down) {
    extern __shared__ uint32_t sm[];
    const uint32_t sb = smem_u32(sm);
    const int tid = threadIdx.x, wid = tid >> 5, lane = tid & 31;
    const int RM = (wid & 3) * 16, CN = (wid >> 2) * 32;
    const int lr = lane >> 2, lk = lane & 3;
    const int b = blockIdx.y, t0 = blockIdx.x * 64;
    const int a = g_adp[b];

    const __half* xb = g_xh + ((size_t)b * T_ + t0) * D_;
    const __half* Wn = g_Wnh + (size_t)a * D_ * R_;

    float c[1][4][4];
#pragma unroll
    for (int nt = 0; nt < 4; nt++)
#pragma unroll
        for (int i = 0; i < 4; i++) c[0][nt][i] = 0.f;

    for (int q = 0; q < 2; q++) {
        issueA64(sb + (uint32_t)(q & 3) * SA64_SZ * 4, xb + q * 32, D_, tid);
        issueBm(sb + (uint32_t)(4 * SA64_SZ + (q & 3) * SM_SZ) * 4, Wn + (size_t)q * 32 * R_, tid);
        CP_COMMIT();
    }
    for (int q = 0; q < 32; q++) {
        if (q + 2 < 32) {
            int p = q + 2;
            issueA64(sb + (uint32_t)(p & 3) * SA64_SZ * 4, xb + p * 32, D_, tid);
            issueBm(sb + (uint32_t)(4 * SA64_SZ + (p & 3) * SM_SZ) * 4, Wn + (size_t)p * 32 * R_, tid);
            CP_COMMIT();
        }
        if (q + 2 < 32) { CP_WAIT(2); } else if (q + 1 < 32) { CP_WAIT(1); } else { CP_WAIT(0); }
        __syncthreads();
        frag_compute<1, 2>(sb + (uint32_t)(q & 3) * SA64_SZ * 4 + RM * 80,
                           sb + (uint32_t)(4 * SA64_SZ + (q & 3) * SM_SZ) * 4 + CN * 2, 144, c, lane);
    }

    {
        int r = RM + lr;
#pragma unroll
        for (int nt = 0; nt < 4; nt++) {
            int col = CN + nt * 8 + lk * 2;
            float bd0 = __ldg(b_down + a * R_ + col);
            float bd1 = __ldg(b_down + a * R_ + col + 1);
            float v0 = c[0][nt][0] + bd0, v1 = c[0][nt][1] + bd1;
            float v2 = c[0][nt][2] + bd0, v3 = c[0][nt][3] + bd1;
            *reinterpret_cast<uint32_t*>(g_midh + ((size_t)b * T_ + t0 + r) * R_ + col) =
                packh2(v0 > 0.f ? v0 : 0.f, v1 > 0.f ? v1 : 0.f);
            *reinterpret_cast<uint32_t*>(g_midh + ((size_t)b * T_ + t0 + r + 8) * R_ + col) =
                packh2(v2 > 0.f ? v2 : 0.f, v3 > 0.f ? v3 : 0.f);
        }
    }
}

// ---------------- out = x@W_base + mid@W_up + biases ----------------
__global__ __launch_bounds__(256)
void out_mma_kernel(const float* __restrict__ b_base, const float* __restrict__ b_up,
                    float* __restrict__ out) {
    extern __shared__ uint32_t sm[];
    const uint32_t sb = smem_u32(sm);
    const int tid = threadIdx.x, wid = tid >> 5, lane = tid & 31;
    const int RM = (wid & 1) * 64, CN = (wid >> 1) * 32;
    const int lr = lane >> 2, lk = lane & 3;
    const int b = blockIdx.z, e0 = blockIdx.y * 128, t0 = blockIdx.x * 128;
    const int a = g_adp[b];

    const __half* xb = g_xh + ((size_t)b * T_ + t0) * D_;
    const __half* mb = g_midh + ((size_t)b * T_ + t0) * R_;
    const __half* Wb = g_Wbh;
    const __half* Wu = g_Wuh + (size_t)a * R_ * D_;

    float c[4][4][4];
#pragma unroll
    for (int mt = 0; mt < 4; mt++)
#pragma unroll
        for (int nt = 0; nt < 4; nt++)
#pragma unroll
            for (int i = 0; i < 4; i++) c[mt][nt][i] = 0.f;

    const int NC = 34;
    for (int q = 0; q < 2; q++) {
        issueA(sb + (uint32_t)(q & 3) * SA_SZ * 4, xb + q * 32, D_, tid);
        issueB(sb + (uint32_t)(OOFF_B + (q & 3) * SB_SZ) * 4, Wb + (size_t)q * 32 * D_ + e0, D_, tid);
        CP_COMMIT();
    }
    for (int q = 0; q < NC; q++) {
        if (q + 2 < NC) {
            int p = q + 2;
            if (p < 32) {
                issueA(sb + (uint32_t)(p & 3) * SA_SZ * 4, xb + p * 32, D_, tid);
                issueB(sb + (uint32_t)(OOFF_B + (p & 3) * SB_SZ) * 4,
                       Wb + (size_t)p * 32 * D_ + e0, D_, tid);
            } else {
                issueA(sb + (uint32_t)(p & 3) * SA_SZ * 4, mb + (p - 32) * 32, R_, tid);
                issueB(sb + (uint32_t)(OOFF_B + (p & 3) * SB_SZ) * 4,
                       Wu + (size_t)(p - 32) * 32 * D_ + e0, D_, tid);
            }
            CP_COMMIT();
        }
        if (q + 2 < NC) { CP_WAIT(2); } else if (q + 1 < NC) { CP_WAIT(1); } else { CP_WAIT(0); }
        __syncthreads();
        frag_compute<4, 2>(sb + (uint32_t)(q & 3) * SA_SZ * 4 + RM * 80,
                           sb + (uint32_t)(OOFF_B + (q & 3) * SB_SZ) * 4 + CN * 2, 272, c, lane);
    }

#pragma unroll
    for (int mt = 0; mt < 4; mt++) {
        int r = RM + mt * 16 + lr;
#pragma unroll
        for (int nt = 0; nt < 4; nt++) {
            int col = e0 + CN + nt * 8 + lk * 2;
            float bb0 = __ldg(b_base + col) + __ldg(b_up + a * D_ + col);
            float bb1 = __ldg(b_base + col + 1) + __ldg(b_up + a * D_ + col + 1);
            float2 v0 = make_float2(c[mt][nt][0] + bb0, c[mt][nt][1] + bb1);
            float2 v1 = make_float2(c[mt][nt][2] + bb0, c[mt][nt][3] + bb1);
            *reinterpret_cast<float2*>(out + ((size_t)b * T_ + t0 + r) * D_ + col) = v0;
            *reinterpret_cast<float2*>(out + ((size_t)b * T_ + t0 + r + 8) * D_ + col) = v1;
        }
    }
}

// ---------------------------------------------------------------------------
extern "C" void kernel_launch(void* const* d_in, const int* in_sizes, int n_in,
                              void* d_out, int out_size) {
    const float* x      = (const float*)d_in[0];
    const float* W_base = (const float*)d_in[1];
    const float* b_base = (const float*)d_in[2];
    const float* W_enc  = (const float*)d_in[3];
    const float* b_enc  = (const float*)d_in[4];
    const float* W_dec  = (const float*)d_in[5];
    const float* b_dec  = (const float*)d_in[6];
    const float* W_down = (const float*)d_in[7];
    const float* b_down = (const float*)d_in[8];
    const float* W_up   = (const float*)d_in[9];
    const float* b_up   = (const float*)d_in[10];
    const int*   cidx   = (const int*)d_in[11];
    float* out = (float*)d_out;

    static bool init = false;
    if (!init) {
        init = true;
        cudaFuncSetAttribute(disc_mma_kernel,
                             cudaFuncAttributeMaxDynamicSharedMemorySize, SMEM_DISC_BYTES);
        cudaFuncSetAttribute(out_mma_kernel,
                             cudaFuncAttributeMaxDynamicSharedMemorySize, SMEM_OUT_BYTES);
        cudaFuncSetAttribute(mid_mma_kernel,
                             cudaFuncAttributeMaxDynamicSharedMemorySize, SMEM_MID_BYTES);
    }

    prep_kernel<<<2048, 256>>>(x, W_enc, W_dec, W_base, W_down, W_up);

    dim3 g1(T_ / 128, B_, N_);
    disc_mma_kernel<<<g1, 256, SMEM_DISC_BYTES>>>(x, b_enc, b_dec, cidx);

    dim3 g2(T_ / 64, B_);
    mid_mma_kernel<<<g2, 256, SMEM_MID_BYTES>>>(b_down);

    dim3 g3(T_ / 128, D_ / 128, B_);
    out_mma_kernel<<<g3, 256, SMEM_OUT_BYTES>>>(b_base, b_up, out);
}